// round 3
// baseline (speedup 1.0000x reference)
#include <cuda_runtime.h>

#define LL 384
#define NN 512
#define DIN 128
#define DOUT 64
#define HEADS 4
#define CHN 16
#define DFF 256
#define NCC (NN*CHN)       /* 8192 */
#define NT (NN*LL)         /* 196608 */
#define EPSV 1e-5f

// ---------------- scratch (device globals; no allocation allowed) ----------------
__device__ float g_attn[HEADS * LL * LL];                     // [h][l][k]
__device__ float g_vt[(size_t)HEADS * LL * NN * CHN];         // [h][k][n*C+c]
__device__ float g_o [(size_t)HEADS * LL * NN * CHN];         // [h][l][n*C+c]
__device__ float g_tmid[(size_t)NT * DOUT];                   // [n*L+l][d]

// ---------------- K1: symmetrize + LayerNorm(128) + pair logits ----------------
// one warp per (i=k, j=l) pair; writes logits to g_attn[h][l=j][k=i]
__global__ void k1_sym_ln_logits(const float* __restrict__ src,
                                 const float* __restrict__ Wp,
                                 const float* __restrict__ bp,
                                 const float* __restrict__ gn,
                                 const float* __restrict__ btn) {
    int lane = threadIdx.x & 31;
    int warp = (blockIdx.x * blockDim.x + threadIdx.x) >> 5;
    int nw   = (gridDim.x * blockDim.x) >> 5;
    int d0 = lane * 4;

    float gg[4], bb[4], wp[4][4], bph[4];
#pragma unroll
    for (int q = 0; q < 4; q++) { gg[q] = gn[d0 + q]; bb[q] = btn[d0 + q]; }
#pragma unroll
    for (int q = 0; q < 4; q++)
#pragma unroll
        for (int h = 0; h < 4; h++) wp[q][h] = Wp[(d0 + q) * 4 + h];
#pragma unroll
    for (int h = 0; h < 4; h++) bph[h] = bp[h];

    for (int p = warp; p < LL * LL; p += nw) {
        int i = p / LL, j = p - i * LL;
        float4 a = *(const float4*)(src + ((size_t)i * LL + j) * DIN + d0);
        float4 b = *(const float4*)(src + ((size_t)j * LL + i) * DIN + d0);
        float s[4];
        s[0] = 0.5f * (a.x + b.x); s[1] = 0.5f * (a.y + b.y);
        s[2] = 0.5f * (a.z + b.z); s[3] = 0.5f * (a.w + b.w);

        float m = s[0] + s[1] + s[2] + s[3];
#pragma unroll
        for (int o = 16; o > 0; o >>= 1) m += __shfl_xor_sync(~0u, m, o);
        m *= (1.0f / 128.0f);

        float dv[4], var = 0.f;
#pragma unroll
        for (int q = 0; q < 4; q++) { dv[q] = s[q] - m; var += dv[q] * dv[q]; }
#pragma unroll
        for (int o = 16; o > 0; o >>= 1) var += __shfl_xor_sync(~0u, var, o);
        float inv = rsqrtf(var * (1.0f / 128.0f) + EPSV);

        float lg[4] = {0.f, 0.f, 0.f, 0.f};
#pragma unroll
        for (int q = 0; q < 4; q++) {
            float y = gg[q] * dv[q] * inv + bb[q];
#pragma unroll
            for (int h = 0; h < 4; h++) lg[h] += y * wp[q][h];
        }
#pragma unroll
        for (int h = 0; h < 4; h++)
#pragma unroll
            for (int o = 16; o > 0; o >>= 1) lg[h] += __shfl_xor_sync(~0u, lg[h], o);

        if (lane == 0) {
#pragma unroll
            for (int h = 0; h < 4; h++)
                g_attn[h * LL * LL + j * LL + i] = lg[h] + bph[h];
        }
    }
}

// ---------------- K2: softmax over k (contiguous 384) per (h,l) row ----------------
__global__ void k2_softmax() {
    int lane = threadIdx.x & 31;
    int row  = (blockIdx.x * blockDim.x + threadIdx.x) >> 5;
    if (row >= HEADS * LL) return;
    float* p = g_attn + (size_t)row * LL;
    float x[12];
    float mx = -1e30f;
#pragma unroll
    for (int q = 0; q < 12; q++) { x[q] = p[lane + q * 32]; mx = fmaxf(mx, x[q]); }
#pragma unroll
    for (int o = 16; o > 0; o >>= 1) mx = fmaxf(mx, __shfl_xor_sync(~0u, mx, o));
    float s = 0.f;
#pragma unroll
    for (int q = 0; q < 12; q++) { x[q] = __expf(x[q] - mx); s += x[q]; }
#pragma unroll
    for (int o = 16; o > 0; o >>= 1) s += __shfl_xor_sync(~0u, s, o);
    float r = 1.0f / s;
#pragma unroll
    for (int q = 0; q < 12; q++) p[lane + q * 32] = x[q] * r;
}

// ---------------- K3: v = LN(tgt; g1,bt1) @ Wm + bm  -> g_vt[h][k][n*C+c] ----------------
__global__ void k3_vproj(const float* __restrict__ tgt,
                         const float* __restrict__ Wm,
                         const float* __restrict__ bm,
                         const float* __restrict__ g1,
                         const float* __restrict__ bt1) {
    __shared__ float sW[64 * 64];
    __shared__ float sy[8][64];
    int tid = threadIdx.x;
    for (int idx = tid; idx < 64 * 64; idx += 256) sW[idx] = Wm[idx];
    __syncthreads();

    int lane = tid & 31, w = tid >> 5;
    int warp = (blockIdx.x * 256 + tid) >> 5;
    int nw   = (gridDim.x * 256) >> 5;

    float g1a = g1[lane * 2], g1b = g1[lane * 2 + 1];
    float b1a = bt1[lane * 2], b1b = bt1[lane * 2 + 1];
    int e0 = lane, e1 = lane + 32;
    float bm0 = bm[e0], bm1 = bm[e1];
    int c0 = e0 >> 2, h0 = e0 & 3;
    int c1 = e1 >> 2, h1 = e1 & 3;

    for (int t = warp; t < NT; t += nw) {
        int n = t / LL, k = t - n * LL;
        float2 x = *(const float2*)(tgt + (size_t)t * 64 + lane * 2);
        float m = x.x + x.y;
#pragma unroll
        for (int o = 16; o > 0; o >>= 1) m += __shfl_xor_sync(~0u, m, o);
        m *= (1.0f / 64.0f);
        float dx0 = x.x - m, dx1 = x.y - m;
        float v = dx0 * dx0 + dx1 * dx1;
#pragma unroll
        for (int o = 16; o > 0; o >>= 1) v += __shfl_xor_sync(~0u, v, o);
        float inv = rsqrtf(v * (1.0f / 64.0f) + EPSV);
        sy[w][lane * 2]     = g1a * dx0 * inv + b1a;
        sy[w][lane * 2 + 1] = g1b * dx1 * inv + b1b;
        __syncwarp();

        float a0 = bm0, a1 = bm1;
#pragma unroll
        for (int i = 0; i < 64; i += 4) {
            float4 yy = *(const float4*)(&sy[w][i]);
            a0 += yy.x * sW[(i + 0) * 64 + e0]; a1 += yy.x * sW[(i + 0) * 64 + e1];
            a0 += yy.y * sW[(i + 1) * 64 + e0]; a1 += yy.y * sW[(i + 1) * 64 + e1];
            a0 += yy.z * sW[(i + 2) * 64 + e0]; a1 += yy.z * sW[(i + 2) * 64 + e1];
            a0 += yy.w * sW[(i + 3) * 64 + e0]; a1 += yy.w * sW[(i + 3) * 64 + e1];
        }
        g_vt[(((size_t)h0 * LL + k) * NN + n) * CHN + c0] = a0;
        g_vt[(((size_t)h1 * LL + k) * NN + n) * CHN + c1] = a1;
        __syncwarp();
    }
}

// ---------------- K4: batched SGEMM  C[h][l][j] = sum_k A[h][l][k] * B[h][k][j] ----------------
// M=384 (l), N=8192 (j=n*C+c), K=384, batch h=4. BM=128, BN=64, BK=16, 8x4 microtile.
__global__ void __launch_bounds__(256) k4_gemm() {
    __shared__ float As[128][20];   // [m][kk], padded
    __shared__ float Bs[16][64];    // [kk][j]
    int h  = blockIdx.z;
    int l0 = blockIdx.y * 128;
    int j0 = blockIdx.x * 64;
    const float* A = g_attn + (size_t)h * LL * LL;
    const float* B = g_vt   + (size_t)h * LL * NCC;
    float*       Cc = g_o   + (size_t)h * LL * NCC;

    int tid = threadIdx.x;
    int tx = tid & 15, ty = tid >> 4;

    float acc[8][4];
#pragma unroll
    for (int i = 0; i < 8; i++)
#pragma unroll
        for (int j = 0; j < 4; j++) acc[i][j] = 0.f;

    for (int k0 = 0; k0 < LL; k0 += 16) {
        // load A tile 128x16 (512 float4, 2 per thread)
#pragma unroll
        for (int r = 0; r < 2; r++) {
            int f = tid * 2 + r;
            int m = f >> 2;
            int kk = (f & 3) * 4;
            float4 v = *(const float4*)(A + (size_t)(l0 + m) * LL + k0 + kk);
            *(float4*)(&As[m][kk]) = v;
        }
        // load B tile 16x64 (256 float4, 1 per thread)
        {
            int row = tid >> 4;
            int c4 = (tid & 15) * 4;
            float4 v = *(const float4*)(B + (size_t)(k0 + row) * NCC + j0 + c4);
            *(float4*)(&Bs[row][c4]) = v;
        }
        __syncthreads();

#pragma unroll
        for (int kk0 = 0; kk0 < 16; kk0 += 4) {
            float av[8][4], bv[4][4];
#pragma unroll
            for (int i = 0; i < 8; i++)
                *(float4*)av[i] = *(const float4*)(&As[ty * 8 + i][kk0]);
#pragma unroll
            for (int q = 0; q < 4; q++)
                *(float4*)bv[q] = *(const float4*)(&Bs[kk0 + q][tx * 4]);
#pragma unroll
            for (int i = 0; i < 8; i++)
#pragma unroll
                for (int q = 0; q < 4; q++)
#pragma unroll
                    for (int j = 0; j < 4; j++)
                        acc[i][j] += av[i][q] * bv[q][j];
        }
        __syncthreads();
    }

#pragma unroll
    for (int i = 0; i < 8; i++) {
        float4 v = make_float4(acc[i][0], acc[i][1], acc[i][2], acc[i][3]);
        *(float4*)(Cc + (size_t)(l0 + ty * 8 + i) * NCC + j0 + tx * 4) = v;
    }
}

// ---------------- K5: tmid = tgt + (gather(o) @ Wo + bo) ----------------
__global__ void k5_oproj(const float* __restrict__ tgt,
                         const float* __restrict__ Wo,
                         const float* __restrict__ bo) {
    __shared__ float sW[64 * 64];
    __shared__ float sy[8][64];
    int tid = threadIdx.x;
    for (int idx = tid; idx < 64 * 64; idx += 256) sW[idx] = Wo[idx];
    __syncthreads();

    int lane = tid & 31, w = tid >> 5;
    int warp = (blockIdx.x * 256 + tid) >> 5;
    int nw   = (gridDim.x * 256) >> 5;

    int e0 = lane, e1 = lane + 32;
    float bo0 = bo[e0], bo1 = bo[e1];
    int c0 = e0 >> 2, h0 = e0 & 3;
    int c1 = e1 >> 2, h1 = e1 & 3;

    for (int t = warp; t < NT; t += nw) {
        int n = t / LL, l = t - n * LL;
        float o0 = g_o[(((size_t)h0 * LL + l) * NN + n) * CHN + c0];
        float o1 = g_o[(((size_t)h1 * LL + l) * NN + n) * CHN + c1];
        sy[w][e0] = o0;
        sy[w][e1] = o1;
        __syncwarp();

        float a0 = bo0, a1 = bo1;
#pragma unroll
        for (int i = 0; i < 64; i += 4) {
            float4 yy = *(const float4*)(&sy[w][i]);
            a0 += yy.x * sW[(i + 0) * 64 + e0]; a1 += yy.x * sW[(i + 0) * 64 + e1];
            a0 += yy.y * sW[(i + 1) * 64 + e0]; a1 += yy.y * sW[(i + 1) * 64 + e1];
            a0 += yy.z * sW[(i + 2) * 64 + e0]; a1 += yy.z * sW[(i + 2) * 64 + e1];
            a0 += yy.w * sW[(i + 3) * 64 + e0]; a1 += yy.w * sW[(i + 3) * 64 + e1];
        }
        g_tmid[(size_t)t * 64 + e0] = tgt[(size_t)t * 64 + e0] + a0;
        g_tmid[(size_t)t * 64 + e1] = tgt[(size_t)t * 64 + e1] + a1;
        __syncwarp();
    }
}

// ---------------- K6: out = tmid + relu(LN(tmid;g2,bt2)@W1+b1)@W2 + b2 ----------------
// weights held in registers: thread tid owns W1 column tid (64 regs) and 64 rows of
// W2 column (tid&63) for hidden chunk (tid>>6) (64 regs).
__global__ void __launch_bounds__(256, 1) k6_ffn(const float* __restrict__ W1,
                                                 const float* __restrict__ b1,
                                                 const float* __restrict__ W2,
                                                 const float* __restrict__ b2,
                                                 const float* __restrict__ g2,
                                                 const float* __restrict__ bt2,
                                                 float* __restrict__ out) {
    __shared__ float sxn[64];
    __shared__ float shid[256];
    __shared__ float spart[256];
    int tid = threadIdx.x;
    int lane = tid & 31;
    int ch = tid >> 6, d = tid & 63;

    float w1r[64], w2r[64];
#pragma unroll
    for (int i = 0; i < 64; i++) w1r[i] = W1[i * 256 + tid];
#pragma unroll
    for (int j = 0; j < 64; j++) w2r[j] = W2[(ch * 64 + j) * 64 + d];
    float b1v = b1[tid];
    float b2v = (tid < 64) ? b2[tid] : 0.f;
    float g2a = 0.f, g2b = 0.f, bt2a = 0.f, bt2b = 0.f;
    if (tid < 32) {
        g2a = g2[lane * 2]; g2b = g2[lane * 2 + 1];
        bt2a = bt2[lane * 2]; bt2b = bt2[lane * 2 + 1];
    }

    for (int t = blockIdx.x; t < NT; t += gridDim.x) {
        const float* xp = g_tmid + (size_t)t * 64;
        if (tid < 32) {
            float2 x = *(const float2*)(xp + lane * 2);
            float m = x.x + x.y;
#pragma unroll
            for (int o = 16; o > 0; o >>= 1) m += __shfl_xor_sync(~0u, m, o);
            m *= (1.0f / 64.0f);
            float dx0 = x.x - m, dx1 = x.y - m;
            float v = dx0 * dx0 + dx1 * dx1;
#pragma unroll
            for (int o = 16; o > 0; o >>= 1) v += __shfl_xor_sync(~0u, v, o);
            float inv = rsqrtf(v * (1.0f / 64.0f) + EPSV);
            sxn[lane * 2]     = g2a * dx0 * inv + bt2a;
            sxn[lane * 2 + 1] = g2b * dx1 * inv + bt2b;
        }
        __syncthreads();

        // hidden[tid] = relu(b1 + sum_i xn[i]*W1[i][tid])
        float ac0 = b1v, ac1 = 0.f, ac2 = 0.f, ac3 = 0.f;
#pragma unroll
        for (int i = 0; i < 64; i += 4) {
            float4 xi = *(const float4*)(sxn + i);
            ac0 += xi.x * w1r[i + 0];
            ac1 += xi.y * w1r[i + 1];
            ac2 += xi.z * w1r[i + 2];
            ac3 += xi.w * w1r[i + 3];
        }
        shid[tid] = fmaxf((ac0 + ac1) + (ac2 + ac3), 0.f);
        __syncthreads();

        // partial out[d] over hidden chunk ch
        float p0 = 0.f, p1 = 0.f, p2 = 0.f, p3 = 0.f;
#pragma unroll
        for (int j = 0; j < 64; j += 4) {
            float4 hj = *(const float4*)(shid + ch * 64 + j);
            p0 += hj.x * w2r[j + 0];
            p1 += hj.y * w2r[j + 1];
            p2 += hj.z * w2r[j + 2];
            p3 += hj.w * w2r[j + 3];
        }
        spart[tid] = (p0 + p1) + (p2 + p3);
        __syncthreads();

        if (tid < 64) {
            float o = xp[tid] + b2v +
                      spart[tid] + spart[tid + 64] + spart[tid + 128] + spart[tid + 192];
            out[(size_t)t * 64 + tid] = o;
        }
        __syncthreads();
    }
}

// ---------------- launch ----------------
extern "C" void kernel_launch(void* const* d_in, const int* in_sizes, int n_in,
                              void* d_out, int out_size) {
    (void)in_sizes; (void)n_in; (void)out_size;
    const float* src  = (const float*)d_in[0];
    const float* tgt  = (const float*)d_in[1];
    const float* Wp   = (const float*)d_in[2];
    const float* bp   = (const float*)d_in[3];
    const float* Wm   = (const float*)d_in[4];
    const float* bm   = (const float*)d_in[5];
    const float* Wo   = (const float*)d_in[6];
    const float* bo   = (const float*)d_in[7];
    const float* W1   = (const float*)d_in[8];
    const float* b1   = (const float*)d_in[9];
    const float* W2   = (const float*)d_in[10];
    const float* b2   = (const float*)d_in[11];
    const float* gn   = (const float*)d_in[12];
    const float* btn  = (const float*)d_in[13];
    const float* g1   = (const float*)d_in[14];
    const float* bt1  = (const float*)d_in[15];
    const float* g2   = (const float*)d_in[16];
    const float* bt2  = (const float*)d_in[17];
    float* out = (float*)d_out;

    k1_sym_ln_logits<<<4608, 256>>>(src, Wp, bp, gn, btn);
    k2_softmax<<<(HEADS * LL + 7) / 8, 256>>>();
    k3_vproj<<<3072, 256>>>(tgt, Wm, bm, g1, bt1);
    k4_gemm<<<dim3(NCC / 64, LL / 128, HEADS), 256>>>();
    k5_oproj<<<3072, 256>>>(tgt, Wo, bo);
    k6_ffn<<<2048, 256>>>(W1, b1, W2, b2, g2, bt2, out);
}

// round 4
// speedup vs baseline: 2.4013x; 2.4013x over previous
#include <cuda_runtime.h>

#define LL 384
#define NN 512
#define DIN 128
#define DOUT 64
#define HEADS 4
#define CHN 16
#define DFF 256
#define NCC (NN*CHN)       /* 8192 */
#define NT (NN*LL)         /* 196608 */
#define EPSV 1e-5f

typedef unsigned long long u64t;

__device__ __forceinline__ u64t dup2(float v) {
    u64t r; asm("mov.b64 %0, {%1, %1};" : "=l"(r) : "f"(v)); return r;
}
__device__ __forceinline__ void ffma2(u64t &d, u64t a, u64t b) {
    asm("fma.rn.f32x2 %0, %1, %2, %0;" : "+l"(d) : "l"(a), "l"(b));
}
__device__ __forceinline__ float2 unpack2(u64t v) {
    float2 f; asm("mov.b64 {%0, %1}, %2;" : "=f"(f.x), "=f"(f.y) : "l"(v)); return f;
}

// ---------------- scratch ----------------
__device__ float g_attn[HEADS * LL * LL];                     // [h][l][k]
__device__ float g_vt[(size_t)HEADS * LL * NN * CHN];         // [h][k][n*C+c]
__device__ float g_o [(size_t)HEADS * LL * NN * CHN];         // [h][l][n*C+c]
__device__ float g_tmid[(size_t)NT * DOUT];                   // [n*L+l][d]

// ---------------- K1: symmetrize + LayerNorm(128) + pair logits ----------------
__global__ void k1_sym_ln_logits(const float* __restrict__ src,
                                 const float* __restrict__ Wp,
                                 const float* __restrict__ bp,
                                 const float* __restrict__ gn,
                                 const float* __restrict__ btn) {
    int lane = threadIdx.x & 31;
    int warp = (blockIdx.x * blockDim.x + threadIdx.x) >> 5;
    int nw   = (gridDim.x * blockDim.x) >> 5;
    int d0 = lane * 4;

    float gg[4], bb[4], wp[4][4], bph[4];
#pragma unroll
    for (int q = 0; q < 4; q++) { gg[q] = gn[d0 + q]; bb[q] = btn[d0 + q]; }
#pragma unroll
    for (int q = 0; q < 4; q++)
#pragma unroll
        for (int h = 0; h < 4; h++) wp[q][h] = Wp[(d0 + q) * 4 + h];
#pragma unroll
    for (int h = 0; h < 4; h++) bph[h] = bp[h];

    for (int p = warp; p < LL * LL; p += nw) {
        int i = p / LL, j = p - i * LL;
        float4 a = *(const float4*)(src + ((size_t)i * LL + j) * DIN + d0);
        float4 b = *(const float4*)(src + ((size_t)j * LL + i) * DIN + d0);
        float s[4];
        s[0] = 0.5f * (a.x + b.x); s[1] = 0.5f * (a.y + b.y);
        s[2] = 0.5f * (a.z + b.z); s[3] = 0.5f * (a.w + b.w);

        float m = s[0] + s[1] + s[2] + s[3];
#pragma unroll
        for (int o = 16; o > 0; o >>= 1) m += __shfl_xor_sync(~0u, m, o);
        m *= (1.0f / 128.0f);

        float dv[4], var = 0.f;
#pragma unroll
        for (int q = 0; q < 4; q++) { dv[q] = s[q] - m; var += dv[q] * dv[q]; }
#pragma unroll
        for (int o = 16; o > 0; o >>= 1) var += __shfl_xor_sync(~0u, var, o);
        float inv = rsqrtf(var * (1.0f / 128.0f) + EPSV);

        float lg[4] = {0.f, 0.f, 0.f, 0.f};
#pragma unroll
        for (int q = 0; q < 4; q++) {
            float y = gg[q] * dv[q] * inv + bb[q];
#pragma unroll
            for (int h = 0; h < 4; h++) lg[h] += y * wp[q][h];
        }
#pragma unroll
        for (int h = 0; h < 4; h++)
#pragma unroll
            for (int o = 16; o > 0; o >>= 1) lg[h] += __shfl_xor_sync(~0u, lg[h], o);

        if (lane == 0) {
#pragma unroll
            for (int h = 0; h < 4; h++)
                g_attn[h * LL * LL + j * LL + i] = lg[h] + bph[h];
        }
    }
}

// ---------------- K2: softmax over k ----------------
__global__ void k2_softmax() {
    int lane = threadIdx.x & 31;
    int row  = (blockIdx.x * blockDim.x + threadIdx.x) >> 5;
    if (row >= HEADS * LL) return;
    float* p = g_attn + (size_t)row * LL;
    float x[12];
    float mx = -1e30f;
#pragma unroll
    for (int q = 0; q < 12; q++) { x[q] = p[lane + q * 32]; mx = fmaxf(mx, x[q]); }
#pragma unroll
    for (int o = 16; o > 0; o >>= 1) mx = fmaxf(mx, __shfl_xor_sync(~0u, mx, o));
    float s = 0.f;
#pragma unroll
    for (int q = 0; q < 12; q++) { x[q] = __expf(x[q] - mx); s += x[q]; }
#pragma unroll
    for (int o = 16; o > 0; o >>= 1) s += __shfl_xor_sync(~0u, s, o);
    float r = 1.0f / s;
#pragma unroll
    for (int q = 0; q < 12; q++) p[lane + q * 32] = x[q] * r;
}

// ---------------- K3: v = LN(tgt) @ Wm + bm -> g_vt[h][k][n*C+c] ----------------
// Block: 128 tokens. smem: Xs[64][132] transposed LN'd input + Ws[64][64].
__global__ void __launch_bounds__(256) k3_vproj(const float* __restrict__ tgt,
                                                const float* __restrict__ Wm,
                                                const float* __restrict__ bm,
                                                const float* __restrict__ g1,
                                                const float* __restrict__ bt1) {
    extern __shared__ float sm3[];
    float* Xs = sm3;             // [64][132]
    float* Ws = sm3 + 64 * 132;  // [64][64]
    int tid = threadIdx.x;
    for (int idx = tid; idx < 4096; idx += 256) Ws[idx] = Wm[idx];

    int lane = tid & 31, w = tid >> 5;
    int t0 = blockIdx.x * 128;
    float g1a = g1[lane * 2], g1b = g1[lane * 2 + 1];
    float ba = bt1[lane * 2], bb = bt1[lane * 2 + 1];
#pragma unroll 4
    for (int s = 0; s < 16; s++) {
        int tt = w * 16 + s;
        float2 x = *(const float2*)(tgt + (size_t)(t0 + tt) * 64 + lane * 2);
        float m = x.x + x.y;
#pragma unroll
        for (int o = 16; o > 0; o >>= 1) m += __shfl_xor_sync(~0u, m, o);
        m *= (1.0f / 64.0f);
        float dx0 = x.x - m, dx1 = x.y - m;
        float v = dx0 * dx0 + dx1 * dx1;
#pragma unroll
        for (int o = 16; o > 0; o >>= 1) v += __shfl_xor_sync(~0u, v, o);
        float inv = rsqrtf(v * (1.0f / 64.0f) + EPSV);
        Xs[(2 * lane) * 132 + tt]     = g1a * dx0 * inv + ba;
        Xs[(2 * lane + 1) * 132 + tt] = g1b * dx1 * inv + bb;
    }
    __syncthreads();

    int tx = tid & 15, ty = tid >> 4;
    float4 bmv = *(const float4*)(bm + tx * 4);
    float acc[8][4];
#pragma unroll
    for (int i = 0; i < 8; i++) {
        acc[i][0] = bmv.x; acc[i][1] = bmv.y; acc[i][2] = bmv.z; acc[i][3] = bmv.w;
    }
#pragma unroll 8
    for (int i = 0; i < 64; i++) {
        float4 a0 = *(const float4*)&Xs[i * 132 + ty * 8];
        float4 a1 = *(const float4*)&Xs[i * 132 + ty * 8 + 4];
        float4 bw = *(const float4*)&Ws[i * 64 + tx * 4];
        float av[8] = {a0.x, a0.y, a0.z, a0.w, a1.x, a1.y, a1.z, a1.w};
#pragma unroll
        for (int r = 0; r < 8; r++) {
            acc[r][0] += av[r] * bw.x; acc[r][1] += av[r] * bw.y;
            acc[r][2] += av[r] * bw.z; acc[r][3] += av[r] * bw.w;
        }
    }
    // scatter: e = tx*4+j -> h=j, c=tx ; token = t0+ty*8+i ; n=bx/3, k=(bx%3)*128+row
    int n = blockIdx.x / 3;
    int kbase = (blockIdx.x % 3) * 128 + ty * 8;
#pragma unroll
    for (int i = 0; i < 8; i++) {
        int k = kbase + i;
#pragma unroll
        for (int j = 0; j < 4; j++)
            g_vt[(((size_t)j * LL + k) * NN + n) * CHN + tx] = acc[i][j];
    }
}

// ---------------- K4: batched SGEMM with packed f32x2 ----------------
// C[h][l][j] = sum_k attn[h][l][k] * vt[h][k][j]; BM=128,BN=64,BK=16.
__global__ void __launch_bounds__(256) k4_gemm() {
    __shared__ float As[16][132];   // [kk][m] transposed
    __shared__ float Bs[16][64];
    int h  = blockIdx.z;
    int l0 = blockIdx.y * 128;
    int j0 = blockIdx.x * 64;
    const float* A  = g_attn + (size_t)h * LL * LL;
    const float* B  = g_vt   + (size_t)h * LL * NCC;
    float*       Cc = g_o    + (size_t)h * LL * NCC;

    int tid = threadIdx.x;
    int tx = tid & 15, ty = tid >> 4;

    u64t acc2[4][4];
#pragma unroll
    for (int rp = 0; rp < 4; rp++)
#pragma unroll
        for (int j = 0; j < 4; j++) acc2[rp][j] = 0ull;

    for (int k0 = 0; k0 < LL; k0 += 16) {
#pragma unroll
        for (int r = 0; r < 2; r++) {
            int f = tid * 2 + r;
            int m = f >> 2;
            int kq = (f & 3) * 4;
            float4 v = *(const float4*)(A + (size_t)(l0 + m) * LL + k0 + kq);
            As[kq + 0][m] = v.x; As[kq + 1][m] = v.y;
            As[kq + 2][m] = v.z; As[kq + 3][m] = v.w;
        }
        {
            int row = tid >> 4;
            int c4 = (tid & 15) * 4;
            *(float4*)&Bs[row][c4] = *(const float4*)(B + (size_t)(k0 + row) * NCC + j0 + c4);
        }
        __syncthreads();

#pragma unroll
        for (int kk = 0; kk < 16; kk++) {
            const u64t* ap = (const u64t*)&As[kk][ty * 8];
            float4 bw = *(const float4*)&Bs[kk][tx * 4];
            u64t bd0 = dup2(bw.x), bd1 = dup2(bw.y), bd2 = dup2(bw.z), bd3 = dup2(bw.w);
#pragma unroll
            for (int rp = 0; rp < 4; rp++) {
                u64t a2 = ap[rp];
                ffma2(acc2[rp][0], a2, bd0);
                ffma2(acc2[rp][1], a2, bd1);
                ffma2(acc2[rp][2], a2, bd2);
                ffma2(acc2[rp][3], a2, bd3);
            }
        }
        __syncthreads();
    }

#pragma unroll
    for (int rp = 0; rp < 4; rp++) {
        float2 v0 = unpack2(acc2[rp][0]);
        float2 v1 = unpack2(acc2[rp][1]);
        float2 v2 = unpack2(acc2[rp][2]);
        float2 v3 = unpack2(acc2[rp][3]);
        int m = l0 + ty * 8 + rp * 2;
        *(float4*)(Cc + (size_t)m * NCC + j0 + tx * 4) =
            make_float4(v0.x, v1.x, v2.x, v3.x);
        *(float4*)(Cc + (size_t)(m + 1) * NCC + j0 + tx * 4) =
            make_float4(v0.y, v1.y, v2.y, v3.y);
    }
}

// ---------------- K5: tmid = tgt + gather(g_o) @ Wo + bo ----------------
__global__ void __launch_bounds__(256) k5_oproj(const float* __restrict__ tgt,
                                                const float* __restrict__ Wo,
                                                const float* __restrict__ bo) {
    extern __shared__ float sm5[];
    float* Xs = sm5;             // [64][132]  Xs[e][t]
    float* Ws = sm5 + 64 * 132;  // [64][64]
    int tid = threadIdx.x;
    for (int idx = tid; idx < 4096; idx += 256) Ws[idx] = Wo[idx];

    int t0 = blockIdx.x * 128;
    int n = blockIdx.x / 3;
    int lbase = (blockIdx.x % 3) * 128;

    // gather: u -> c4=u&3, h=(u>>2)&3, tok=(u>>4); 8 passes of 16 tokens
    {
        int c4 = tid & 3, hh = (tid >> 2) & 3, tg = tid >> 4;
#pragma unroll
        for (int p = 0; p < 8; p++) {
            int tt = p * 16 + tg;
            int l = lbase + tt;
            float4 v = *(const float4*)(g_o + (((size_t)hh * LL + l) * NN + n) * CHN + c4 * 4);
            int e0 = (c4 * 4) * 4 + hh;  // e = c*4 + h, c = c4*4+cc
            Xs[(e0 + 0) * 132 + tt] = v.x;
            Xs[(e0 + 4) * 132 + tt] = v.y;
            Xs[(e0 + 8) * 132 + tt] = v.z;
            Xs[(e0 + 12) * 132 + tt] = v.w;
        }
    }
    __syncthreads();

    int tx = tid & 15, ty = tid >> 4;
    float4 bov = *(const float4*)(bo + tx * 4);
    float acc[8][4];
#pragma unroll
    for (int i = 0; i < 8; i++) {
        acc[i][0] = bov.x; acc[i][1] = bov.y; acc[i][2] = bov.z; acc[i][3] = bov.w;
    }
#pragma unroll 8
    for (int i = 0; i < 64; i++) {
        float4 a0 = *(const float4*)&Xs[i * 132 + ty * 8];
        float4 a1 = *(const float4*)&Xs[i * 132 + ty * 8 + 4];
        float4 bw = *(const float4*)&Ws[i * 64 + tx * 4];
        float av[8] = {a0.x, a0.y, a0.z, a0.w, a1.x, a1.y, a1.z, a1.w};
#pragma unroll
        for (int r = 0; r < 8; r++) {
            acc[r][0] += av[r] * bw.x; acc[r][1] += av[r] * bw.y;
            acc[r][2] += av[r] * bw.z; acc[r][3] += av[r] * bw.w;
        }
    }
#pragma unroll
    for (int i = 0; i < 8; i++) {
        int t = t0 + ty * 8 + i;
        float4 rsd = *(const float4*)(tgt + (size_t)t * 64 + tx * 4);
        float4 ov = make_float4(acc[i][0] + rsd.x, acc[i][1] + rsd.y,
                                acc[i][2] + rsd.z, acc[i][3] + rsd.w);
        *(float4*)(g_tmid + (size_t)t * 64 + tx * 4) = ov;
    }
}

// ---------------- K6: fused FFN: out = tmid + relu(LN(tmid)@W1+b1)@W2+b2 ----------------
// Block: 128 tokens. smem: Xn[64][132] + Hs[64][132] + W1s[64][256] + W2s[256][64].
__global__ void __launch_bounds__(256) k6_ffn(const float* __restrict__ W1,
                                              const float* __restrict__ b1,
                                              const float* __restrict__ W2,
                                              const float* __restrict__ b2,
                                              const float* __restrict__ g2,
                                              const float* __restrict__ bt2,
                                              float* __restrict__ out) {
    extern __shared__ float sm6[];
    float* Xn  = sm6;                 // [64][132]  Xn[feat][t]
    float* Hs  = Xn + 64 * 132;       // [64][132]  Hs[f_local][t]
    float* W1s = Hs + 64 * 132;       // [64][256]
    float* W2s = W1s + 64 * 256;      // [256][64]
    int tid = threadIdx.x;
    for (int idx = tid; idx < 16384; idx += 256) W1s[idx] = W1[idx];
    for (int idx = tid; idx < 16384; idx += 256) W2s[idx] = W2[idx];

    int lane = tid & 31, w = tid >> 5;
    int t0 = blockIdx.x * 128;
    float g2a = g2[lane * 2], g2b = g2[lane * 2 + 1];
    float ba = bt2[lane * 2], bb = bt2[lane * 2 + 1];
#pragma unroll 4
    for (int s = 0; s < 16; s++) {
        int tt = w * 16 + s;
        float2 x = *(const float2*)(g_tmid + (size_t)(t0 + tt) * 64 + lane * 2);
        float m = x.x + x.y;
#pragma unroll
        for (int o = 16; o > 0; o >>= 1) m += __shfl_xor_sync(~0u, m, o);
        m *= (1.0f / 64.0f);
        float dx0 = x.x - m, dx1 = x.y - m;
        float v = dx0 * dx0 + dx1 * dx1;
#pragma unroll
        for (int o = 16; o > 0; o >>= 1) v += __shfl_xor_sync(~0u, v, o);
        float inv = rsqrtf(v * (1.0f / 64.0f) + EPSV);
        Xn[(2 * lane) * 132 + tt]     = g2a * dx0 * inv + ba;
        Xn[(2 * lane + 1) * 132 + tt] = g2b * dx1 * inv + bb;
    }
    __syncthreads();

    int tx = tid & 15, ty = tid >> 4;
    u64t acc2[4][4];
#pragma unroll
    for (int rp = 0; rp < 4; rp++)
#pragma unroll
        for (int j = 0; j < 4; j++) acc2[rp][j] = 0ull;

    for (int ffc = 0; ffc < 4; ffc++) {
        // GEMM1: H[t][f] = relu(b1 + sum_i Xn[i][t] * W1[i][ffc*64+f])
        float4 b1v = *(const float4*)(b1 + ffc * 64 + tx * 4);
        u64t h2[4][4];
#pragma unroll
        for (int rp = 0; rp < 4; rp++) {
            h2[rp][0] = dup2(b1v.x); h2[rp][1] = dup2(b1v.y);
            h2[rp][2] = dup2(b1v.z); h2[rp][3] = dup2(b1v.w);
        }
#pragma unroll 8
        for (int i = 0; i < 64; i++) {
            const u64t* ap = (const u64t*)&Xn[i * 132 + ty * 8];
            float4 bw = *(const float4*)&W1s[i * 256 + ffc * 64 + tx * 4];
            u64t bd0 = dup2(bw.x), bd1 = dup2(bw.y), bd2 = dup2(bw.z), bd3 = dup2(bw.w);
#pragma unroll
            for (int rp = 0; rp < 4; rp++) {
                u64t a2 = ap[rp];
                ffma2(h2[rp][0], a2, bd0);
                ffma2(h2[rp][1], a2, bd1);
                ffma2(h2[rp][2], a2, bd2);
                ffma2(h2[rp][3], a2, bd3);
            }
        }
        // relu + store transposed Hs[f][t]
#pragma unroll
        for (int rp = 0; rp < 4; rp++)
#pragma unroll
            for (int j = 0; j < 4; j++) {
                float2 v = unpack2(h2[rp][j]);
                v.x = fmaxf(v.x, 0.f);
                v.y = fmaxf(v.y, 0.f);
                *(float2*)&Hs[(tx * 4 + j) * 132 + ty * 8 + rp * 2] = v;
            }
        __syncthreads();

        // GEMM2: acc += H[t][f] * W2[ffc*64+f][o]
#pragma unroll 8
        for (int f = 0; f < 64; f++) {
            const u64t* ap = (const u64t*)&Hs[f * 132 + ty * 8];
            float4 bw = *(const float4*)&W2s[(ffc * 64 + f) * 64 + tx * 4];
            u64t bd0 = dup2(bw.x), bd1 = dup2(bw.y), bd2 = dup2(bw.z), bd3 = dup2(bw.w);
#pragma unroll
            for (int rp = 0; rp < 4; rp++) {
                u64t a2 = ap[rp];
                ffma2(acc2[rp][0], a2, bd0);
                ffma2(acc2[rp][1], a2, bd1);
                ffma2(acc2[rp][2], a2, bd2);
                ffma2(acc2[rp][3], a2, bd3);
            }
        }
        __syncthreads();
    }

    float4 b2v = *(const float4*)(b2 + tx * 4);
#pragma unroll
    for (int rp = 0; rp < 4; rp++) {
        int t = t0 + ty * 8 + rp * 2;
        float4 r0 = *(const float4*)(g_tmid + (size_t)t * 64 + tx * 4);
        float4 r1 = *(const float4*)(g_tmid + (size_t)(t + 1) * 64 + tx * 4);
        float2 v0 = unpack2(acc2[rp][0]);
        float2 v1 = unpack2(acc2[rp][1]);
        float2 v2 = unpack2(acc2[rp][2]);
        float2 v3 = unpack2(acc2[rp][3]);
        *(float4*)(out + (size_t)t * 64 + tx * 4) = make_float4(
            r0.x + b2v.x + v0.x, r0.y + b2v.y + v1.x,
            r0.z + b2v.z + v2.x, r0.w + b2v.w + v3.x);
        *(float4*)(out + (size_t)(t + 1) * 64 + tx * 4) = make_float4(
            r1.x + b2v.x + v0.y, r1.y + b2v.y + v1.y,
            r1.z + b2v.z + v2.y, r1.w + b2v.w + v3.y);
    }
}

// ---------------- launch ----------------
#define SM3_BYTES ((64 * 132 + 64 * 64) * 4)
#define SM6_BYTES ((64 * 132 * 2 + 64 * 256 + 256 * 64) * 4)

extern "C" void kernel_launch(void* const* d_in, const int* in_sizes, int n_in,
                              void* d_out, int out_size) {
    (void)in_sizes; (void)n_in; (void)out_size;
    const float* src  = (const float*)d_in[0];
    const float* tgt  = (const float*)d_in[1];
    const float* Wp   = (const float*)d_in[2];
    const float* bp   = (const float*)d_in[3];
    const float* Wm   = (const float*)d_in[4];
    const float* bm   = (const float*)d_in[5];
    const float* Wo   = (const float*)d_in[6];
    const float* bo   = (const float*)d_in[7];
    const float* W1   = (const float*)d_in[8];
    const float* b1   = (const float*)d_in[9];
    const float* W2   = (const float*)d_in[10];
    const float* b2   = (const float*)d_in[11];
    const float* gn   = (const float*)d_in[12];
    const float* btn  = (const float*)d_in[13];
    const float* g1   = (const float*)d_in[14];
    const float* bt1  = (const float*)d_in[15];
    const float* g2   = (const float*)d_in[16];
    const float* bt2  = (const float*)d_in[17];
    float* out = (float*)d_out;

    static bool inited = false;
    if (!inited) {
        cudaFuncSetAttribute(k3_vproj, cudaFuncAttributeMaxDynamicSharedMemorySize, SM3_BYTES);
        cudaFuncSetAttribute(k5_oproj, cudaFuncAttributeMaxDynamicSharedMemorySize, SM3_BYTES);
        cudaFuncSetAttribute(k6_ffn,   cudaFuncAttributeMaxDynamicSharedMemorySize, SM6_BYTES);
        inited = true;
    }

    k1_sym_ln_logits<<<4608, 256>>>(src, Wp, bp, gn, btn);
    k2_softmax<<<(HEADS * LL + 7) / 8, 256>>>();
    k3_vproj<<<NT / 128, 256, SM3_BYTES>>>(tgt, Wm, bm, g1, bt1);
    k4_gemm<<<dim3(NCC / 64, LL / 128, HEADS), 256>>>();
    k5_oproj<<<NT / 128, 256, SM3_BYTES>>>(tgt, Wo, bo);
    k6_ffn<<<NT / 128, 256, SM6_BYTES>>>(W1, b1, W2, b2, g2, bt2, out);
}

// round 7
// speedup vs baseline: 2.5228x; 1.0506x over previous
#include <cuda_runtime.h>

#define LL 384
#define NN 512
#define DIN 128
#define DOUT 64
#define HEADS 4
#define CHN 16
#define DFF 256
#define NCC (NN*CHN)       /* 8192 */
#define NT (NN*LL)         /* 196608 */
#define EPSV 1e-5f

typedef unsigned long long u64t;

__device__ __forceinline__ u64t dup2(float v) {
    u64t r; asm("mov.b64 %0, {%1, %1};" : "=l"(r) : "f"(v)); return r;
}
__device__ __forceinline__ void ffma2(u64t &d, u64t a, u64t b) {
    asm("fma.rn.f32x2 %0, %1, %2, %0;" : "+l"(d) : "l"(a), "l"(b));
}
__device__ __forceinline__ float2 unpack2(u64t v) {
    float2 f; asm("mov.b64 {%0, %1}, %2;" : "=f"(f.x), "=f"(f.y) : "l"(v)); return f;
}

// ---------------- scratch ----------------
__device__ float g_attn[HEADS * LL * LL];                     // [h][l][k]
__device__ float g_vt[(size_t)HEADS * LL * NN * CHN];         // [h][k][n*C+c]
__device__ float g_o [(size_t)HEADS * LL * NN * CHN];         // [h][l][n*C+c]
__device__ float g_tmid[(size_t)NT * DOUT];                   // [n*L+l][d]

// ---------------- K1: symmetrize + LayerNorm(128) + pair logits (i<=j only) ----------------
__global__ void k1_sym_ln_logits(const float* __restrict__ src,
                                 const float* __restrict__ Wp,
                                 const float* __restrict__ bp,
                                 const float* __restrict__ gn,
                                 const float* __restrict__ btn) {
    int lane = threadIdx.x & 31;
    int warp = (blockIdx.x * blockDim.x + threadIdx.x) >> 5;
    int nw   = (gridDim.x * blockDim.x) >> 5;
    int d0 = lane * 4;

    float gg[4], bb[4], wp[4][4], bph[4];
#pragma unroll
    for (int q = 0; q < 4; q++) { gg[q] = gn[d0 + q]; bb[q] = btn[d0 + q]; }
#pragma unroll
    for (int q = 0; q < 4; q++)
#pragma unroll
        for (int h = 0; h < 4; h++) wp[q][h] = Wp[(d0 + q) * 4 + h];
#pragma unroll
    for (int h = 0; h < 4; h++) bph[h] = bp[h];

    for (int p = warp; p < LL * LL; p += nw) {
        int i = p / LL, j = p - i * LL;
        if (i > j) continue;   // symmetric: logits(i,j)==logits(j,i)
        float4 a = *(const float4*)(src + ((size_t)i * LL + j) * DIN + d0);
        float4 b = *(const float4*)(src + ((size_t)j * LL + i) * DIN + d0);
        float s[4];
        s[0] = 0.5f * (a.x + b.x); s[1] = 0.5f * (a.y + b.y);
        s[2] = 0.5f * (a.z + b.z); s[3] = 0.5f * (a.w + b.w);

        float m = s[0] + s[1] + s[2] + s[3];
#pragma unroll
        for (int o = 16; o > 0; o >>= 1) m += __shfl_xor_sync(~0u, m, o);
        m *= (1.0f / 128.0f);

        float dv[4], var = 0.f;
#pragma unroll
        for (int q = 0; q < 4; q++) { dv[q] = s[q] - m; var += dv[q] * dv[q]; }
#pragma unroll
        for (int o = 16; o > 0; o >>= 1) var += __shfl_xor_sync(~0u, var, o);
        float inv = rsqrtf(var * (1.0f / 128.0f) + EPSV);

        float lg[4] = {0.f, 0.f, 0.f, 0.f};
#pragma unroll
        for (int q = 0; q < 4; q++) {
            float y = gg[q] * dv[q] * inv + bb[q];
#pragma unroll
            for (int h = 0; h < 4; h++) lg[h] += y * wp[q][h];
        }
#pragma unroll
        for (int h = 0; h < 4; h++)
#pragma unroll
            for (int o = 16; o > 0; o >>= 1) lg[h] += __shfl_xor_sync(~0u, lg[h], o);

        if (lane == 0) {
#pragma unroll
            for (int h = 0; h < 4; h++) {
                float v = lg[h] + bph[h];
                g_attn[h * LL * LL + j * LL + i] = v;
                g_attn[h * LL * LL + i * LL + j] = v;
            }
        }
    }
}

// ---------------- K2: softmax over k ----------------
__global__ void k2_softmax() {
    int lane = threadIdx.x & 31;
    int row  = (blockIdx.x * blockDim.x + threadIdx.x) >> 5;
    if (row >= HEADS * LL) return;
    float* p = g_attn + (size_t)row * LL;
    float x[12];
    float mx = -1e30f;
#pragma unroll
    for (int q = 0; q < 12; q++) { x[q] = p[lane + q * 32]; mx = fmaxf(mx, x[q]); }
#pragma unroll
    for (int o = 16; o > 0; o >>= 1) mx = fmaxf(mx, __shfl_xor_sync(~0u, mx, o));
    float s = 0.f;
#pragma unroll
    for (int q = 0; q < 12; q++) { x[q] = __expf(x[q] - mx); s += x[q]; }
#pragma unroll
    for (int o = 16; o > 0; o >>= 1) s += __shfl_xor_sync(~0u, s, o);
    float r = 1.0f / s;
#pragma unroll
    for (int q = 0; q < 12; q++) p[lane + q * 32] = x[q] * r;
}

// ---------------- K3: v = LN(tgt) @ Wm + bm -> g_vt[h][k][n*C+c] (FFMA2) ----------------
__global__ void __launch_bounds__(256) k3_vproj(const float* __restrict__ tgt,
                                                const float* __restrict__ Wm,
                                                const float* __restrict__ bm,
                                                const float* __restrict__ g1,
                                                const float* __restrict__ bt1) {
    extern __shared__ float sm3[];
    float* Xs = sm3;             // [64][132]  Xs[feat][token]
    float* Ws = sm3 + 64 * 132;  // [64][64]
    int tid = threadIdx.x;
    for (int idx = tid; idx < 4096; idx += 256) Ws[idx] = Wm[idx];

    int lane = tid & 31, w = tid >> 5;
    int t0 = blockIdx.x * 128;
    float g1a = g1[lane * 2], g1b = g1[lane * 2 + 1];
    float ba = bt1[lane * 2], bb = bt1[lane * 2 + 1];
#pragma unroll 4
    for (int s = 0; s < 16; s++) {
        int tt = w * 16 + s;
        float2 x = *(const float2*)(tgt + (size_t)(t0 + tt) * 64 + lane * 2);
        float m = x.x + x.y;
#pragma unroll
        for (int o = 16; o > 0; o >>= 1) m += __shfl_xor_sync(~0u, m, o);
        m *= (1.0f / 64.0f);
        float dx0 = x.x - m, dx1 = x.y - m;
        float v = dx0 * dx0 + dx1 * dx1;
#pragma unroll
        for (int o = 16; o > 0; o >>= 1) v += __shfl_xor_sync(~0u, v, o);
        float inv = rsqrtf(v * (1.0f / 64.0f) + EPSV);
        Xs[(2 * lane) * 132 + tt]     = g1a * dx0 * inv + ba;
        Xs[(2 * lane + 1) * 132 + tt] = g1b * dx1 * inv + bb;
    }
    __syncthreads();

    int tx = tid & 15, ty = tid >> 4;
    float4 bmv = *(const float4*)(bm + tx * 4);
    u64t acc2[4][4];
#pragma unroll
    for (int rp = 0; rp < 4; rp++) {
        acc2[rp][0] = dup2(bmv.x); acc2[rp][1] = dup2(bmv.y);
        acc2[rp][2] = dup2(bmv.z); acc2[rp][3] = dup2(bmv.w);
    }
#pragma unroll 8
    for (int i = 0; i < 64; i++) {
        const u64t* ap = (const u64t*)&Xs[i * 132 + ty * 8];
        float4 bw = *(const float4*)&Ws[i * 64 + tx * 4];
        u64t bd0 = dup2(bw.x), bd1 = dup2(bw.y), bd2 = dup2(bw.z), bd3 = dup2(bw.w);
#pragma unroll
        for (int rp = 0; rp < 4; rp++) {
            u64t a2 = ap[rp];
            ffma2(acc2[rp][0], a2, bd0);
            ffma2(acc2[rp][1], a2, bd1);
            ffma2(acc2[rp][2], a2, bd2);
            ffma2(acc2[rp][3], a2, bd3);
        }
    }
    // scatter: col e = tx*4+j -> h=j, c=tx; token pair = (kbase+2rp, +1)
    int n = blockIdx.x / 3;
    int kbase = (blockIdx.x % 3) * 128 + ty * 8;
#pragma unroll
    for (int rp = 0; rp < 4; rp++) {
        int k = kbase + rp * 2;
#pragma unroll
        for (int j = 0; j < 4; j++) {
            float2 v = unpack2(acc2[rp][j]);
            g_vt[(((size_t)j * LL + k)     * NN + n) * CHN + tx] = v.x;
            g_vt[(((size_t)j * LL + k + 1) * NN + n) * CHN + tx] = v.y;
        }
    }
}

// ---------------- K4: batched SGEMM f32x2, BM=128 BN=128 BK=16, 8x8 microtile ----------------
__global__ void __launch_bounds__(256) k4_gemm() {
    __shared__ float As[16][132];   // [kk][m] transposed
    __shared__ float Bs[16][128];
    int h  = blockIdx.z;
    int l0 = blockIdx.y * 128;
    int j0 = blockIdx.x * 128;
    const float* A  = g_attn + (size_t)h * LL * LL;
    const float* B  = g_vt   + (size_t)h * LL * NCC;
    float*       Cc = g_o    + (size_t)h * LL * NCC;

    int tid = threadIdx.x;
    int tx = tid & 15, ty = tid >> 4;

    u64t acc2[4][8];
#pragma unroll
    for (int rp = 0; rp < 4; rp++)
#pragma unroll
        for (int j = 0; j < 8; j++) acc2[rp][j] = 0ull;

    for (int k0 = 0; k0 < LL; k0 += 16) {
#pragma unroll
        for (int r = 0; r < 2; r++) {
            int f = tid + r * 256;
            int m = f >> 2;
            int kq = (f & 3) * 4;
            float4 v = *(const float4*)(A + (size_t)(l0 + m) * LL + k0 + kq);
            As[kq + 0][m] = v.x; As[kq + 1][m] = v.y;
            As[kq + 2][m] = v.z; As[kq + 3][m] = v.w;
        }
#pragma unroll
        for (int r = 0; r < 2; r++) {
            int f = tid + r * 256;
            int row = f >> 5;
            int c4 = (f & 31) * 4;
            *(float4*)&Bs[row][c4] = *(const float4*)(B + (size_t)(k0 + row) * NCC + j0 + c4);
        }
        __syncthreads();

#pragma unroll
        for (int kk = 0; kk < 16; kk++) {
            const u64t* ap = (const u64t*)&As[kk][ty * 8];
            float4 bw0 = *(const float4*)&Bs[kk][tx * 8];
            float4 bw1 = *(const float4*)&Bs[kk][tx * 8 + 4];
            u64t bd[8];
            bd[0] = dup2(bw0.x); bd[1] = dup2(bw0.y); bd[2] = dup2(bw0.z); bd[3] = dup2(bw0.w);
            bd[4] = dup2(bw1.x); bd[5] = dup2(bw1.y); bd[6] = dup2(bw1.z); bd[7] = dup2(bw1.w);
#pragma unroll
            for (int rp = 0; rp < 4; rp++) {
                u64t a2 = ap[rp];
#pragma unroll
                for (int j = 0; j < 8; j++) ffma2(acc2[rp][j], a2, bd[j]);
            }
        }
        __syncthreads();
    }

#pragma unroll
    for (int rp = 0; rp < 4; rp++) {
        float2 v[8];
#pragma unroll
        for (int j = 0; j < 8; j++) v[j] = unpack2(acc2[rp][j]);
        int m = l0 + ty * 8 + rp * 2;
        float* c0 = Cc + (size_t)m * NCC + j0 + tx * 8;
        float* c1 = Cc + (size_t)(m + 1) * NCC + j0 + tx * 8;
        *(float4*)(c0)     = make_float4(v[0].x, v[1].x, v[2].x, v[3].x);
        *(float4*)(c0 + 4) = make_float4(v[4].x, v[5].x, v[6].x, v[7].x);
        *(float4*)(c1)     = make_float4(v[0].y, v[1].y, v[2].y, v[3].y);
        *(float4*)(c1 + 4) = make_float4(v[4].y, v[5].y, v[6].y, v[7].y);
    }
}

// ---------------- K5: tmid = tgt + gather(g_o) @ Wo + bo (FFMA2) ----------------
__global__ void __launch_bounds__(256) k5_oproj(const float* __restrict__ tgt,
                                                const float* __restrict__ Wo,
                                                const float* __restrict__ bo) {
    extern __shared__ float sm5[];
    float* Xs = sm5;             // [64][132]  Xs[e][t]
    float* Ws = sm5 + 64 * 132;  // [64][64]
    int tid = threadIdx.x;
    for (int idx = tid; idx < 4096; idx += 256) Ws[idx] = Wo[idx];

    int t0 = blockIdx.x * 128;
    int n = blockIdx.x / 3;
    int lbase = (blockIdx.x % 3) * 128;

    {
        int c4 = tid & 3, hh = (tid >> 2) & 3, tg = tid >> 4;
#pragma unroll
        for (int p = 0; p < 8; p++) {
            int tt = p * 16 + tg;
            int l = lbase + tt;
            float4 v = *(const float4*)(g_o + (((size_t)hh * LL + l) * NN + n) * CHN + c4 * 4);
            int e0 = (c4 * 4) * 4 + hh;
            Xs[(e0 + 0) * 132 + tt] = v.x;
            Xs[(e0 + 4) * 132 + tt] = v.y;
            Xs[(e0 + 8) * 132 + tt] = v.z;
            Xs[(e0 + 12) * 132 + tt] = v.w;
        }
    }
    __syncthreads();

    int tx = tid & 15, ty = tid >> 4;
    float4 bov = *(const float4*)(bo + tx * 4);
    u64t acc2[4][4];
#pragma unroll
    for (int rp = 0; rp < 4; rp++) {
        acc2[rp][0] = dup2(bov.x); acc2[rp][1] = dup2(bov.y);
        acc2[rp][2] = dup2(bov.z); acc2[rp][3] = dup2(bov.w);
    }
#pragma unroll 8
    for (int i = 0; i < 64; i++) {
        const u64t* ap = (const u64t*)&Xs[i * 132 + ty * 8];
        float4 bw = *(const float4*)&Ws[i * 64 + tx * 4];
        u64t bd0 = dup2(bw.x), bd1 = dup2(bw.y), bd2 = dup2(bw.z), bd3 = dup2(bw.w);
#pragma unroll
        for (int rp = 0; rp < 4; rp++) {
            u64t a2 = ap[rp];
            ffma2(acc2[rp][0], a2, bd0);
            ffma2(acc2[rp][1], a2, bd1);
            ffma2(acc2[rp][2], a2, bd2);
            ffma2(acc2[rp][3], a2, bd3);
        }
    }
#pragma unroll
    for (int rp = 0; rp < 4; rp++) {
        int t = t0 + ty * 8 + rp * 2;
        float2 v0 = unpack2(acc2[rp][0]);
        float2 v1 = unpack2(acc2[rp][1]);
        float2 v2 = unpack2(acc2[rp][2]);
        float2 v3 = unpack2(acc2[rp][3]);
        float4 r0 = *(const float4*)(tgt + (size_t)t * 64 + tx * 4);
        float4 r1 = *(const float4*)(tgt + (size_t)(t + 1) * 64 + tx * 4);
        *(float4*)(g_tmid + (size_t)t * 64 + tx * 4) =
            make_float4(r0.x + v0.x, r0.y + v1.x, r0.z + v2.x, r0.w + v3.x);
        *(float4*)(g_tmid + (size_t)(t + 1) * 64 + tx * 4) =
            make_float4(r1.x + v0.y, r1.y + v1.y, r1.z + v2.y, r1.w + v3.y);
    }
}

// ---------------- K6: fused FFN, hidden in 2 chunks of 128 ----------------
// smem: Xn[64][132] + Hs[128][132] + W1c[64][128] + W2c[128][64]
__global__ void __launch_bounds__(256, 1) k6_ffn(const float* __restrict__ W1,
                                                 const float* __restrict__ b1,
                                                 const float* __restrict__ W2,
                                                 const float* __restrict__ b2,
                                                 const float* __restrict__ g2,
                                                 const float* __restrict__ bt2,
                                                 float* __restrict__ out) {
    extern __shared__ float sm6[];
    float* Xn  = sm6;                  // [64][132]
    float* Hs  = Xn + 64 * 132;        // [128][132]
    float* W1c = Hs + 128 * 132;       // [64][128]
    float* W2c = W1c + 64 * 128;       // [128][64]
    int tid = threadIdx.x;
    int lane = tid & 31, w = tid >> 5;
    int t0 = blockIdx.x * 128;

    // LN -> Xn (transposed, token-pairs contiguous)
    float g2a = g2[lane * 2], g2b = g2[lane * 2 + 1];
    float ba = bt2[lane * 2], bb = bt2[lane * 2 + 1];
#pragma unroll 4
    for (int s = 0; s < 16; s++) {
        int tt = w * 16 + s;
        float2 x = *(const float2*)(g_tmid + (size_t)(t0 + tt) * 64 + lane * 2);
        float m = x.x + x.y;
#pragma unroll
        for (int o = 16; o > 0; o >>= 1) m += __shfl_xor_sync(~0u, m, o);
        m *= (1.0f / 64.0f);
        float dx0 = x.x - m, dx1 = x.y - m;
        float v = dx0 * dx0 + dx1 * dx1;
#pragma unroll
        for (int o = 16; o > 0; o >>= 1) v += __shfl_xor_sync(~0u, v, o);
        float inv = rsqrtf(v * (1.0f / 64.0f) + EPSV);
        Xn[(2 * lane) * 132 + tt]     = g2a * dx0 * inv + ba;
        Xn[(2 * lane + 1) * 132 + tt] = g2b * dx1 * inv + bb;
    }

    int tx = tid & 15, ty = tid >> 4;
    u64t acc2[4][4];
#pragma unroll
    for (int rp = 0; rp < 4; rp++)
#pragma unroll
        for (int j = 0; j < 4; j++) acc2[rp][j] = 0ull;

    for (int step = 0; step < 2; step++) {
        int hbase = step * 128;
        // stage weight chunks
#pragma unroll
        for (int p = 0; p < 8; p++) {
            int f = tid + p * 256;
            int row = f >> 5;
            int c4 = (f & 31) * 4;
            *(float4*)&W1c[row * 128 + c4] = *(const float4*)(W1 + row * 256 + hbase + c4);
        }
#pragma unroll
        for (int p = 0; p < 8; p++) {
            int f = (tid + p * 256) * 4;
            *(float4*)&W2c[f] = *(const float4*)(W2 + hbase * 64 + f);
        }
        __syncthreads();

        // GEMM1: H[128 tok][128 hid] = relu(Xn^T @ W1c + b1)
        float4 b10 = *(const float4*)(b1 + hbase + tx * 8);
        float4 b11 = *(const float4*)(b1 + hbase + tx * 8 + 4);
        u64t h2[4][8];
#pragma unroll
        for (int rp = 0; rp < 4; rp++) {
            h2[rp][0] = dup2(b10.x); h2[rp][1] = dup2(b10.y);
            h2[rp][2] = dup2(b10.z); h2[rp][3] = dup2(b10.w);
            h2[rp][4] = dup2(b11.x); h2[rp][5] = dup2(b11.y);
            h2[rp][6] = dup2(b11.z); h2[rp][7] = dup2(b11.w);
        }
#pragma unroll 8
        for (int i = 0; i < 64; i++) {
            const u64t* ap = (const u64t*)&Xn[i * 132 + ty * 8];
            float4 bw0 = *(const float4*)&W1c[i * 128 + tx * 8];
            float4 bw1 = *(const float4*)&W1c[i * 128 + tx * 8 + 4];
            u64t bd[8];
            bd[0] = dup2(bw0.x); bd[1] = dup2(bw0.y); bd[2] = dup2(bw0.z); bd[3] = dup2(bw0.w);
            bd[4] = dup2(bw1.x); bd[5] = dup2(bw1.y); bd[6] = dup2(bw1.z); bd[7] = dup2(bw1.w);
#pragma unroll
            for (int rp = 0; rp < 4; rp++) {
                u64t a2 = ap[rp];
#pragma unroll
                for (int j = 0; j < 8; j++) ffma2(h2[rp][j], a2, bd[j]);
            }
        }
        // relu + store transposed Hs[f][t]
#pragma unroll
        for (int rp = 0; rp < 4; rp++)
#pragma unroll
            for (int j = 0; j < 8; j++) {
                float2 v = unpack2(h2[rp][j]);
                v.x = fmaxf(v.x, 0.f);
                v.y = fmaxf(v.y, 0.f);
                *(float2*)&Hs[(tx * 8 + j) * 132 + ty * 8 + rp * 2] = v;
            }
        __syncthreads();

        // GEMM2: acc2 += Hs^T @ W2c  (K=128)
#pragma unroll 8
        for (int f = 0; f < 128; f++) {
            const u64t* ap = (const u64t*)&Hs[f * 132 + ty * 8];
            float4 bw = *(const float4*)&W2c[f * 64 + tx * 4];
            u64t bd0 = dup2(bw.x), bd1 = dup2(bw.y), bd2 = dup2(bw.z), bd3 = dup2(bw.w);
#pragma unroll
            for (int rp = 0; rp < 4; rp++) {
                u64t a2 = ap[rp];
                ffma2(acc2[rp][0], a2, bd0);
                ffma2(acc2[rp][1], a2, bd1);
                ffma2(acc2[rp][2], a2, bd2);
                ffma2(acc2[rp][3], a2, bd3);
            }
        }
        __syncthreads();
    }

    float4 b2v = *(const float4*)(b2 + tx * 4);
#pragma unroll
    for (int rp = 0; rp < 4; rp++) {
        int t = t0 + ty * 8 + rp * 2;
        float4 r0 = *(const float4*)(g_tmid + (size_t)t * 64 + tx * 4);
        float4 r1 = *(const float4*)(g_tmid + (size_t)(t + 1) * 64 + tx * 4);
        float2 v0 = unpack2(acc2[rp][0]);
        float2 v1 = unpack2(acc2[rp][1]);
        float2 v2 = unpack2(acc2[rp][2]);
        float2 v3 = unpack2(acc2[rp][3]);
        *(float4*)(out + (size_t)t * 64 + tx * 4) = make_float4(
            r0.x + b2v.x + v0.x, r0.y + b2v.y + v1.x,
            r0.z + b2v.z + v2.x, r0.w + b2v.w + v3.x);
        *(float4*)(out + (size_t)(t + 1) * 64 + tx * 4) = make_float4(
            r1.x + b2v.x + v0.y, r1.y + b2v.y + v1.y,
            r1.z + b2v.z + v2.y, r1.w + b2v.w + v3.y);
    }
}

// ---------------- launch ----------------
#define SM3_BYTES ((64 * 132 + 64 * 64) * 4)
#define SM6_BYTES ((64 * 132 + 128 * 132 + 64 * 128 + 128 * 64) * 4)

extern "C" void kernel_launch(void* const* d_in, const int* in_sizes, int n_in,
                              void* d_out, int out_size) {
    (void)in_sizes; (void)n_in; (void)out_size;
    const float* src  = (const float*)d_in[0];
    const float* tgt  = (const float*)d_in[1];
    const float* Wp   = (const float*)d_in[2];
    const float* bp   = (const float*)d_in[3];
    const float* Wm   = (const float*)d_in[4];
    const float* bm   = (const float*)d_in[5];
    const float* Wo   = (const float*)d_in[6];
    const float* bo   = (const float*)d_in[7];
    const float* W1   = (const float*)d_in[8];
    const float* b1   = (const float*)d_in[9];
    const float* W2   = (const float*)d_in[10];
    const float* b2   = (const float*)d_in[11];
    const float* gn   = (const float*)d_in[12];
    const float* btn  = (const float*)d_in[13];
    const float* g1   = (const float*)d_in[14];
    const float* bt1  = (const float*)d_in[15];
    const float* g2   = (const float*)d_in[16];
    const float* bt2  = (const float*)d_in[17];
    float* out = (float*)d_out;

    static bool inited = false;
    if (!inited) {
        cudaFuncSetAttribute(k3_vproj, cudaFuncAttributeMaxDynamicSharedMemorySize, SM3_BYTES);
        cudaFuncSetAttribute(k5_oproj, cudaFuncAttributeMaxDynamicSharedMemorySize, SM3_BYTES);
        cudaFuncSetAttribute(k6_ffn,   cudaFuncAttributeMaxDynamicSharedMemorySize, SM6_BYTES);
        inited = true;
    }

    k1_sym_ln_logits<<<4608, 256>>>(src, Wp, bp, gn, btn);
    k2_softmax<<<(HEADS * LL + 7) / 8, 256>>>();
    k3_vproj<<<NT / 128, 256, SM3_BYTES>>>(tgt, Wm, bm, g1, bt1);
    k4_gemm<<<dim3(NCC / 128, LL / 128, HEADS), 256>>>();
    k5_oproj<<<NT / 128, 256, SM3_BYTES>>>(tgt, Wo, bo);
    k6_ffn<<<NT / 128, 256, SM6_BYTES>>>(W1, b1, W2, b2, g2, bt2, out);
}

// round 8
// speedup vs baseline: 2.7276x; 1.0812x over previous
#include <cuda_runtime.h>

#define LL 384
#define NN 512
#define DIN 128
#define DOUT 64
#define HEADS 4
#define CHN 16
#define DFF 256
#define NCC (NN*CHN)       /* 8192 */
#define NT (NN*LL)         /* 196608 */
#define EPSV 1e-5f

typedef unsigned long long u64t;

__device__ __forceinline__ u64t dup2(float v) {
    u64t r; asm("mov.b64 %0, {%1, %1};" : "=l"(r) : "f"(v)); return r;
}
__device__ __forceinline__ void ffma2(u64t &d, u64t a, u64t b) {
    asm("fma.rn.f32x2 %0, %1, %2, %0;" : "+l"(d) : "l"(a), "l"(b));
}
__device__ __forceinline__ float2 unpack2(u64t v) {
    float2 f; asm("mov.b64 {%0, %1}, %2;" : "=f"(f.x), "=f"(f.y) : "l"(v)); return f;
}

// ---------------- scratch ----------------
__device__ float g_attn[HEADS * LL * LL];                     // [h][l][k]
__device__ float g_vt[(size_t)HEADS * LL * NN * CHN];         // [h][k][n*C+c]
__device__ float g_o [(size_t)HEADS * LL * NN * CHN];         // [h][l][n*C+c]
__device__ float g_tmid[(size_t)NT * DOUT];                   // [n*L+l][d]

// ---------------- K1: symmetrize + LayerNorm(128) + pair logits (i<=j only) ----------------
__global__ void k1_sym_ln_logits(const float* __restrict__ src,
                                 const float* __restrict__ Wp,
                                 const float* __restrict__ bp,
                                 const float* __restrict__ gn,
                                 const float* __restrict__ btn) {
    int lane = threadIdx.x & 31;
    int warp = (blockIdx.x * blockDim.x + threadIdx.x) >> 5;
    int nw   = (gridDim.x * blockDim.x) >> 5;
    int d0 = lane * 4;

    float gg[4], bb[4], wp[4][4], bph[4];
#pragma unroll
    for (int q = 0; q < 4; q++) { gg[q] = gn[d0 + q]; bb[q] = btn[d0 + q]; }
#pragma unroll
    for (int q = 0; q < 4; q++)
#pragma unroll
        for (int h = 0; h < 4; h++) wp[q][h] = Wp[(d0 + q) * 4 + h];
#pragma unroll
    for (int h = 0; h < 4; h++) bph[h] = bp[h];

    for (int p = warp; p < LL * LL; p += nw) {
        int i = p / LL, j = p - i * LL;
        if (i > j) continue;
        float4 a = *(const float4*)(src + ((size_t)i * LL + j) * DIN + d0);
        float4 b = *(const float4*)(src + ((size_t)j * LL + i) * DIN + d0);
        float s[4];
        s[0] = 0.5f * (a.x + b.x); s[1] = 0.5f * (a.y + b.y);
        s[2] = 0.5f * (a.z + b.z); s[3] = 0.5f * (a.w + b.w);

        float m = s[0] + s[1] + s[2] + s[3];
#pragma unroll
        for (int o = 16; o > 0; o >>= 1) m += __shfl_xor_sync(~0u, m, o);
        m *= (1.0f / 128.0f);

        float dv[4], var = 0.f;
#pragma unroll
        for (int q = 0; q < 4; q++) { dv[q] = s[q] - m; var += dv[q] * dv[q]; }
#pragma unroll
        for (int o = 16; o > 0; o >>= 1) var += __shfl_xor_sync(~0u, var, o);
        float inv = rsqrtf(var * (1.0f / 128.0f) + EPSV);

        float lg[4] = {0.f, 0.f, 0.f, 0.f};
#pragma unroll
        for (int q = 0; q < 4; q++) {
            float y = gg[q] * dv[q] * inv + bb[q];
#pragma unroll
            for (int h = 0; h < 4; h++) lg[h] += y * wp[q][h];
        }
#pragma unroll
        for (int h = 0; h < 4; h++)
#pragma unroll
            for (int o = 16; o > 0; o >>= 1) lg[h] += __shfl_xor_sync(~0u, lg[h], o);

        if (lane == 0) {
#pragma unroll
            for (int h = 0; h < 4; h++) {
                float v = lg[h] + bph[h];
                g_attn[h * LL * LL + j * LL + i] = v;
                g_attn[h * LL * LL + i * LL + j] = v;
            }
        }
    }
}

// ---------------- K2: softmax over k ----------------
__global__ void k2_softmax() {
    int lane = threadIdx.x & 31;
    int row  = (blockIdx.x * blockDim.x + threadIdx.x) >> 5;
    if (row >= HEADS * LL) return;
    float* p = g_attn + (size_t)row * LL;
    float x[12];
    float mx = -1e30f;
#pragma unroll
    for (int q = 0; q < 12; q++) { x[q] = p[lane + q * 32]; mx = fmaxf(mx, x[q]); }
#pragma unroll
    for (int o = 16; o > 0; o >>= 1) mx = fmaxf(mx, __shfl_xor_sync(~0u, mx, o));
    float s = 0.f;
#pragma unroll
    for (int q = 0; q < 12; q++) { x[q] = __expf(x[q] - mx); s += x[q]; }
#pragma unroll
    for (int o = 16; o > 0; o >>= 1) s += __shfl_xor_sync(~0u, s, o);
    float r = 1.0f / s;
#pragma unroll
    for (int q = 0; q < 12; q++) p[lane + q * 32] = x[q] * r;
}

// ---------------- K3: v = LN(tgt) @ Wm + bm -> g_vt[h][k][n*C+c] (FFMA2) ----------------
__global__ void __launch_bounds__(256) k3_vproj(const float* __restrict__ tgt,
                                                const float* __restrict__ Wm,
                                                const float* __restrict__ bm,
                                                const float* __restrict__ g1,
                                                const float* __restrict__ bt1) {
    extern __shared__ float sm3[];
    float* Xs = sm3;             // [64][132]
    float* Ws = sm3 + 64 * 132;  // [64][64]
    int tid = threadIdx.x;
    for (int idx = tid; idx < 4096; idx += 256) Ws[idx] = Wm[idx];

    int lane = tid & 31, w = tid >> 5;
    int t0 = blockIdx.x * 128;
    float g1a = g1[lane * 2], g1b = g1[lane * 2 + 1];
    float ba = bt1[lane * 2], bb = bt1[lane * 2 + 1];
#pragma unroll 4
    for (int s = 0; s < 16; s++) {
        int tt = w * 16 + s;
        float2 x = *(const float2*)(tgt + (size_t)(t0 + tt) * 64 + lane * 2);
        float m = x.x + x.y;
#pragma unroll
        for (int o = 16; o > 0; o >>= 1) m += __shfl_xor_sync(~0u, m, o);
        m *= (1.0f / 64.0f);
        float dx0 = x.x - m, dx1 = x.y - m;
        float v = dx0 * dx0 + dx1 * dx1;
#pragma unroll
        for (int o = 16; o > 0; o >>= 1) v += __shfl_xor_sync(~0u, v, o);
        float inv = rsqrtf(v * (1.0f / 64.0f) + EPSV);
        Xs[(2 * lane) * 132 + tt]     = g1a * dx0 * inv + ba;
        Xs[(2 * lane + 1) * 132 + tt] = g1b * dx1 * inv + bb;
    }
    __syncthreads();

    int tx = tid & 15, ty = tid >> 4;
    float4 bmv = *(const float4*)(bm + tx * 4);
    u64t acc2[4][4];
#pragma unroll
    for (int rp = 0; rp < 4; rp++) {
        acc2[rp][0] = dup2(bmv.x); acc2[rp][1] = dup2(bmv.y);
        acc2[rp][2] = dup2(bmv.z); acc2[rp][3] = dup2(bmv.w);
    }
#pragma unroll 8
    for (int i = 0; i < 64; i++) {
        const u64t* ap = (const u64t*)&Xs[i * 132 + ty * 8];
        float4 bw = *(const float4*)&Ws[i * 64 + tx * 4];
        u64t bd0 = dup2(bw.x), bd1 = dup2(bw.y), bd2 = dup2(bw.z), bd3 = dup2(bw.w);
#pragma unroll
        for (int rp = 0; rp < 4; rp++) {
            u64t a2 = ap[rp];
            ffma2(acc2[rp][0], a2, bd0);
            ffma2(acc2[rp][1], a2, bd1);
            ffma2(acc2[rp][2], a2, bd2);
            ffma2(acc2[rp][3], a2, bd3);
        }
    }
    int n = blockIdx.x / 3;
    int kbase = (blockIdx.x % 3) * 128 + ty * 8;
#pragma unroll
    for (int rp = 0; rp < 4; rp++) {
        int k = kbase + rp * 2;
#pragma unroll
        for (int j = 0; j < 4; j++) {
            float2 v = unpack2(acc2[rp][j]);
            g_vt[(((size_t)j * LL + k)     * NN + n) * CHN + tx] = v.x;
            g_vt[(((size_t)j * LL + k + 1) * NN + n) * CHN + tx] = v.y;
        }
    }
}

// ---------------- K4: batched SGEMM f32x2, BM=128 BN=64 BK=32, double-buffered ----------------
#define K4_ABUF (32 * 132)
#define K4_BBUF (32 * 64)
#define K4_SMEM ((2 * K4_ABUF + 2 * K4_BBUF) * 4)
__global__ void __launch_bounds__(256) k4_gemm() {
    extern __shared__ float sm4[];
    float* AsBase = sm4;                 // [2][32][132] (As[k][m] transposed)
    float* BsBase = sm4 + 2 * K4_ABUF;   // [2][32][64]
    int h  = blockIdx.z;
    int l0 = blockIdx.y * 128;
    int j0 = blockIdx.x * 64;
    const float* A  = g_attn + (size_t)h * LL * LL;
    const float* B  = g_vt   + (size_t)h * LL * NCC;
    float*       Cc = g_o    + (size_t)h * LL * NCC;

    int tid = threadIdx.x;
    int tx = tid & 15, ty = tid >> 4;

    u64t acc2[4][4];
#pragma unroll
    for (int rp = 0; rp < 4; rp++)
#pragma unroll
        for (int j = 0; j < 4; j++) acc2[rp][j] = 0ull;

    float4 ar[4], br[2];
    // prologue: load tile 0
#pragma unroll
    for (int r = 0; r < 4; r++) {
        int f = tid + r * 256;
        ar[r] = *(const float4*)(A + (size_t)(l0 + (f >> 3)) * LL + (f & 7) * 4);
    }
#pragma unroll
    for (int r = 0; r < 2; r++) {
        int f = tid + r * 256;
        br[r] = *(const float4*)(B + (size_t)(f >> 4) * NCC + j0 + (f & 15) * 4);
    }
    {
        float* Ab = AsBase; float* Bb = BsBase;
#pragma unroll
        for (int r = 0; r < 4; r++) {
            int f = tid + r * 256; int m = f >> 3; int k = (f & 7) * 4;
            Ab[(k + 0) * 132 + m] = ar[r].x; Ab[(k + 1) * 132 + m] = ar[r].y;
            Ab[(k + 2) * 132 + m] = ar[r].z; Ab[(k + 3) * 132 + m] = ar[r].w;
        }
#pragma unroll
        for (int r = 0; r < 2; r++) {
            int f = tid + r * 256;
            *(float4*)&Bb[(f >> 4) * 64 + (f & 15) * 4] = br[r];
        }
    }
    __syncthreads();

    for (int t = 0; t < 12; t++) {
        int cur = t & 1;
        if (t < 11) {
            int k0 = (t + 1) * 32;
#pragma unroll
            for (int r = 0; r < 4; r++) {
                int f = tid + r * 256;
                ar[r] = *(const float4*)(A + (size_t)(l0 + (f >> 3)) * LL + k0 + (f & 7) * 4);
            }
#pragma unroll
            for (int r = 0; r < 2; r++) {
                int f = tid + r * 256;
                br[r] = *(const float4*)(B + (size_t)(k0 + (f >> 4)) * NCC + j0 + (f & 15) * 4);
            }
        }
        const float* Ab = AsBase + cur * K4_ABUF;
        const float* Bb = BsBase + cur * K4_BBUF;
#pragma unroll 8
        for (int kk = 0; kk < 32; kk++) {
            const u64t* ap = (const u64t*)&Ab[kk * 132 + ty * 8];
            float4 bw = *(const float4*)&Bb[kk * 64 + tx * 4];
            u64t bd0 = dup2(bw.x), bd1 = dup2(bw.y), bd2 = dup2(bw.z), bd3 = dup2(bw.w);
#pragma unroll
            for (int rp = 0; rp < 4; rp++) {
                u64t a2 = ap[rp];
                ffma2(acc2[rp][0], a2, bd0);
                ffma2(acc2[rp][1], a2, bd1);
                ffma2(acc2[rp][2], a2, bd2);
                ffma2(acc2[rp][3], a2, bd3);
            }
        }
        if (t < 11) {
            int nb = cur ^ 1;
            float* Ab2 = AsBase + nb * K4_ABUF;
            float* Bb2 = BsBase + nb * K4_BBUF;
#pragma unroll
            for (int r = 0; r < 4; r++) {
                int f = tid + r * 256; int m = f >> 3; int k = (f & 7) * 4;
                Ab2[(k + 0) * 132 + m] = ar[r].x; Ab2[(k + 1) * 132 + m] = ar[r].y;
                Ab2[(k + 2) * 132 + m] = ar[r].z; Ab2[(k + 3) * 132 + m] = ar[r].w;
            }
#pragma unroll
            for (int r = 0; r < 2; r++) {
                int f = tid + r * 256;
                *(float4*)&Bb2[(f >> 4) * 64 + (f & 15) * 4] = br[r];
            }
        }
        __syncthreads();
    }

#pragma unroll
    for (int rp = 0; rp < 4; rp++) {
        float2 v0 = unpack2(acc2[rp][0]);
        float2 v1 = unpack2(acc2[rp][1]);
        float2 v2 = unpack2(acc2[rp][2]);
        float2 v3 = unpack2(acc2[rp][3]);
        int m = l0 + ty * 8 + rp * 2;
        *(float4*)(Cc + (size_t)m * NCC + j0 + tx * 4) =
            make_float4(v0.x, v1.x, v2.x, v3.x);
        *(float4*)(Cc + (size_t)(m + 1) * NCC + j0 + tx * 4) =
            make_float4(v0.y, v1.y, v2.y, v3.y);
    }
}

// ---------------- K5: tmid = tgt + gather(g_o) @ Wo + bo (FFMA2) ----------------
__global__ void __launch_bounds__(256) k5_oproj(const float* __restrict__ tgt,
                                                const float* __restrict__ Wo,
                                                const float* __restrict__ bo) {
    extern __shared__ float sm5[];
    float* Xs = sm5;             // [64][132]  Xs[e][t]
    float* Ws = sm5 + 64 * 132;  // [64][64]
    int tid = threadIdx.x;
    for (int idx = tid; idx < 4096; idx += 256) Ws[idx] = Wo[idx];

    int t0 = blockIdx.x * 128;
    int n = blockIdx.x / 3;
    int lbase = (blockIdx.x % 3) * 128;

    {
        int c4 = tid & 3, hh = (tid >> 2) & 3, tg = tid >> 4;
#pragma unroll
        for (int p = 0; p < 8; p++) {
            int tt = p * 16 + tg;
            int l = lbase + tt;
            float4 v = *(const float4*)(g_o + (((size_t)hh * LL + l) * NN + n) * CHN + c4 * 4);
            int e0 = (c4 * 4) * 4 + hh;
            Xs[(e0 + 0) * 132 + tt] = v.x;
            Xs[(e0 + 4) * 132 + tt] = v.y;
            Xs[(e0 + 8) * 132 + tt] = v.z;
            Xs[(e0 + 12) * 132 + tt] = v.w;
        }
    }
    __syncthreads();

    int tx = tid & 15, ty = tid >> 4;
    float4 bov = *(const float4*)(bo + tx * 4);
    u64t acc2[4][4];
#pragma unroll
    for (int rp = 0; rp < 4; rp++) {
        acc2[rp][0] = dup2(bov.x); acc2[rp][1] = dup2(bov.y);
        acc2[rp][2] = dup2(bov.z); acc2[rp][3] = dup2(bov.w);
    }
#pragma unroll 8
    for (int i = 0; i < 64; i++) {
        const u64t* ap = (const u64t*)&Xs[i * 132 + ty * 8];
        float4 bw = *(const float4*)&Ws[i * 64 + tx * 4];
        u64t bd0 = dup2(bw.x), bd1 = dup2(bw.y), bd2 = dup2(bw.z), bd3 = dup2(bw.w);
#pragma unroll
        for (int rp = 0; rp < 4; rp++) {
            u64t a2 = ap[rp];
            ffma2(acc2[rp][0], a2, bd0);
            ffma2(acc2[rp][1], a2, bd1);
            ffma2(acc2[rp][2], a2, bd2);
            ffma2(acc2[rp][3], a2, bd3);
        }
    }
#pragma unroll
    for (int rp = 0; rp < 4; rp++) {
        int t = t0 + ty * 8 + rp * 2;
        float2 v0 = unpack2(acc2[rp][0]);
        float2 v1 = unpack2(acc2[rp][1]);
        float2 v2 = unpack2(acc2[rp][2]);
        float2 v3 = unpack2(acc2[rp][3]);
        float4 r0 = *(const float4*)(tgt + (size_t)t * 64 + tx * 4);
        float4 r1 = *(const float4*)(tgt + (size_t)(t + 1) * 64 + tx * 4);
        *(float4*)(g_tmid + (size_t)t * 64 + tx * 4) =
            make_float4(r0.x + v0.x, r0.y + v1.x, r0.z + v2.x, r0.w + v3.x);
        *(float4*)(g_tmid + (size_t)(t + 1) * 64 + tx * 4) =
            make_float4(r1.x + v0.y, r1.y + v1.y, r1.z + v2.y, r1.w + v3.y);
    }
}

// ---------------- K6: fused FFN, hidden in 2 chunks of 128, swizzled Hs ----------------
__global__ void __launch_bounds__(256, 1) k6_ffn(const float* __restrict__ W1,
                                                 const float* __restrict__ b1,
                                                 const float* __restrict__ W2,
                                                 const float* __restrict__ b2,
                                                 const float* __restrict__ g2,
                                                 const float* __restrict__ bt2,
                                                 float* __restrict__ out) {
    extern __shared__ float sm6[];
    float* Xn  = sm6;                  // [64][132]
    float* Hs  = Xn + 64 * 132;        // [128][132] (column-swizzled)
    float* W1c = Hs + 128 * 132;       // [64][128]
    float* W2c = W1c + 64 * 128;       // [128][64]
    int tid = threadIdx.x;
    int lane = tid & 31, w = tid >> 5;
    int t0 = blockIdx.x * 128;

    float g2a = g2[lane * 2], g2b = g2[lane * 2 + 1];
    float ba = bt2[lane * 2], bb = bt2[lane * 2 + 1];
#pragma unroll 4
    for (int s = 0; s < 16; s++) {
        int tt = w * 16 + s;
        float2 x = *(const float2*)(g_tmid + (size_t)(t0 + tt) * 64 + lane * 2);
        float m = x.x + x.y;
#pragma unroll
        for (int o = 16; o > 0; o >>= 1) m += __shfl_xor_sync(~0u, m, o);
        m *= (1.0f / 64.0f);
        float dx0 = x.x - m, dx1 = x.y - m;
        float v = dx0 * dx0 + dx1 * dx1;
#pragma unroll
        for (int o = 16; o > 0; o >>= 1) v += __shfl_xor_sync(~0u, v, o);
        float inv = rsqrtf(v * (1.0f / 64.0f) + EPSV);
        Xn[(2 * lane) * 132 + tt]     = g2a * dx0 * inv + ba;
        Xn[(2 * lane + 1) * 132 + tt] = g2b * dx1 * inv + bb;
    }

    int tx = tid & 15, ty = tid >> 4;
    u64t acc2[4][4];
#pragma unroll
    for (int rp = 0; rp < 4; rp++)
#pragma unroll
        for (int j = 0; j < 4; j++) acc2[rp][j] = 0ull;

    for (int step = 0; step < 2; step++) {
        int hbase = step * 128;
#pragma unroll
        for (int p = 0; p < 8; p++) {
            int f = tid + p * 256;
            int row = f >> 5;
            int c4 = (f & 31) * 4;
            *(float4*)&W1c[row * 128 + c4] = *(const float4*)(W1 + row * 256 + hbase + c4);
        }
#pragma unroll
        for (int p = 0; p < 8; p++) {
            int f = (tid + p * 256) * 4;
            *(float4*)&W2c[f] = *(const float4*)(W2 + hbase * 64 + f);
        }
        __syncthreads();

        // GEMM1: H[128 tok][128 hid] = relu(Xn^T @ W1c + b1)
        float4 b10 = *(const float4*)(b1 + hbase + tx * 8);
        float4 b11 = *(const float4*)(b1 + hbase + tx * 8 + 4);
        u64t h2[4][8];
#pragma unroll
        for (int rp = 0; rp < 4; rp++) {
            h2[rp][0] = dup2(b10.x); h2[rp][1] = dup2(b10.y);
            h2[rp][2] = dup2(b10.z); h2[rp][3] = dup2(b10.w);
            h2[rp][4] = dup2(b11.x); h2[rp][5] = dup2(b11.y);
            h2[rp][6] = dup2(b11.z); h2[rp][7] = dup2(b11.w);
        }
#pragma unroll 8
        for (int i = 0; i < 64; i++) {
            const u64t* ap = (const u64t*)&Xn[i * 132 + ty * 8];
            float4 bw0 = *(const float4*)&W1c[i * 128 + tx * 8];
            float4 bw1 = *(const float4*)&W1c[i * 128 + tx * 8 + 4];
            u64t bd[8];
            bd[0] = dup2(bw0.x); bd[1] = dup2(bw0.y); bd[2] = dup2(bw0.z); bd[3] = dup2(bw0.w);
            bd[4] = dup2(bw1.x); bd[5] = dup2(bw1.y); bd[6] = dup2(bw1.z); bd[7] = dup2(bw1.w);
#pragma unroll
            for (int rp = 0; rp < 4; rp++) {
                u64t a2 = ap[rp];
#pragma unroll
                for (int j = 0; j < 8; j++) ffma2(h2[rp][j], a2, bd[j]);
            }
        }
        // relu + store swizzled transposed Hs[f][(ty^tx)*8 + rp*2]
#pragma unroll
        for (int rp = 0; rp < 4; rp++)
#pragma unroll
            for (int j = 0; j < 8; j++) {
                float2 v = unpack2(h2[rp][j]);
                v.x = fmaxf(v.x, 0.f);
                v.y = fmaxf(v.y, 0.f);
                *(float2*)&Hs[(tx * 8 + j) * 132 + ((ty ^ tx) * 8 + rp * 2)] = v;
            }
        __syncthreads();

        // GEMM2: acc2 += Hs^T @ W2c  (K=128), de-swizzled loads
#pragma unroll 8
        for (int f = 0; f < 128; f++) {
            int u = (f >> 3) & 15;
            const u64t* ap = (const u64t*)&Hs[f * 132 + ((ty ^ u) * 8)];
            float4 bw = *(const float4*)&W2c[f * 64 + tx * 4];
            u64t bd0 = dup2(bw.x), bd1 = dup2(bw.y), bd2 = dup2(bw.z), bd3 = dup2(bw.w);
#pragma unroll
            for (int rp = 0; rp < 4; rp++) {
                u64t a2 = ap[rp];
                ffma2(acc2[rp][0], a2, bd0);
                ffma2(acc2[rp][1], a2, bd1);
                ffma2(acc2[rp][2], a2, bd2);
                ffma2(acc2[rp][3], a2, bd3);
            }
        }
        __syncthreads();
    }

    float4 b2v = *(const float4*)(b2 + tx * 4);
#pragma unroll
    for (int rp = 0; rp < 4; rp++) {
        int t = t0 + ty * 8 + rp * 2;
        float4 r0 = *(const float4*)(g_tmid + (size_t)t * 64 + tx * 4);
        float4 r1 = *(const float4*)(g_tmid + (size_t)(t + 1) * 64 + tx * 4);
        float2 v0 = unpack2(acc2[rp][0]);
        float2 v1 = unpack2(acc2[rp][1]);
        float2 v2 = unpack2(acc2[rp][2]);
        float2 v3 = unpack2(acc2[rp][3]);
        *(float4*)(out + (size_t)t * 64 + tx * 4) = make_float4(
            r0.x + b2v.x + v0.x, r0.y + b2v.y + v1.x,
            r0.z + b2v.z + v2.x, r0.w + b2v.w + v3.x);
        *(float4*)(out + (size_t)(t + 1) * 64 + tx * 4) = make_float4(
            r1.x + b2v.x + v0.y, r1.y + b2v.y + v1.y,
            r1.z + b2v.z + v2.y, r1.w + b2v.w + v3.y);
    }
}

// ---------------- launch ----------------
#define SM3_BYTES ((64 * 132 + 64 * 64) * 4)
#define SM6_BYTES ((64 * 132 + 128 * 132 + 64 * 128 + 128 * 64) * 4)

extern "C" void kernel_launch(void* const* d_in, const int* in_sizes, int n_in,
                              void* d_out, int out_size) {
    (void)in_sizes; (void)n_in; (void)out_size;
    const float* src  = (const float*)d_in[0];
    const float* tgt  = (const float*)d_in[1];
    const float* Wp   = (const float*)d_in[2];
    const float* bp   = (const float*)d_in[3];
    const float* Wm   = (const float*)d_in[4];
    const float* bm   = (const float*)d_in[5];
    const float* Wo   = (const float*)d_in[6];
    const float* bo   = (const float*)d_in[7];
    const float* W1   = (const float*)d_in[8];
    const float* b1   = (const float*)d_in[9];
    const float* W2   = (const float*)d_in[10];
    const float* b2   = (const float*)d_in[11];
    const float* gn   = (const float*)d_in[12];
    const float* btn  = (const float*)d_in[13];
    const float* g1   = (const float*)d_in[14];
    const float* bt1  = (const float*)d_in[15];
    const float* g2   = (const float*)d_in[16];
    const float* bt2  = (const float*)d_in[17];
    float* out = (float*)d_out;

    static bool inited = false;
    if (!inited) {
        cudaFuncSetAttribute(k3_vproj, cudaFuncAttributeMaxDynamicSharedMemorySize, SM3_BYTES);
        cudaFuncSetAttribute(k4_gemm,  cudaFuncAttributeMaxDynamicSharedMemorySize, K4_SMEM);
        cudaFuncSetAttribute(k5_oproj, cudaFuncAttributeMaxDynamicSharedMemorySize, SM3_BYTES);
        cudaFuncSetAttribute(k6_ffn,   cudaFuncAttributeMaxDynamicSharedMemorySize, SM6_BYTES);
        inited = true;
    }

    k1_sym_ln_logits<<<4608, 256>>>(src, Wp, bp, gn, btn);
    k2_softmax<<<(HEADS * LL + 7) / 8, 256>>>();
    k3_vproj<<<NT / 128, 256, SM3_BYTES>>>(tgt, Wm, bm, g1, bt1);
    k4_gemm<<<dim3(NCC / 64, LL / 128, HEADS), 256, K4_SMEM>>>();
    k5_oproj<<<NT / 128, 256, SM3_BYTES>>>(tgt, Wo, bo);
    k6_ffn<<<NT / 128, 256, SM6_BYTES>>>(W1, b1, W2, b2, g2, bt2, out);
}

// round 14
// speedup vs baseline: 3.5278x; 1.2934x over previous
#include <cuda_runtime.h>
#include <cuda_bf16.h>
#include <cstdint>

#define LL 384
#define NN 512
#define DIN 128
#define DOUT 64
#define HEADS 4
#define CHN 16
#define DFF 256
#define NCC (NN*CHN)       /* 8192 */
#define NT (NN*LL)         /* 196608 */
#define EPSV 1e-5f

typedef unsigned long long u64t;

__device__ __forceinline__ u64t dup2(float v) {
    u64t r; asm("mov.b64 %0, {%1, %1};" : "=l"(r) : "f"(v)); return r;
}
__device__ __forceinline__ void ffma2(u64t &d, u64t a, u64t b) {
    asm("fma.rn.f32x2 %0, %1, %2, %0;" : "+l"(d) : "l"(a), "l"(b));
}
__device__ __forceinline__ float2 unpack2(u64t v) {
    float2 f; asm("mov.b64 {%0, %1}, %2;" : "=f"(f.x), "=f"(f.y) : "l"(v)); return f;
}
__device__ __forceinline__ uint32_t smem_u32(const void* p) {
    uint32_t a;
    asm("{ .reg .u64 t; cvta.to.shared.u64 t, %1; cvt.u32.u64 %0, t; }" : "=r"(a) : "l"(p));
    return a;
}
__device__ __forceinline__ void cp_async16(uint32_t s, const void* g) {
    asm volatile("cp.async.cg.shared.global [%0], [%1], 16;" :: "r"(s), "l"(g));
}
#define CP_COMMIT() asm volatile("cp.async.commit_group;" ::: "memory")
#define CP_WAIT0()  asm volatile("cp.async.wait_group 0;" ::: "memory")

#define LDMX4(d0, d1, d2, d3, addr) \
    asm volatile("ldmatrix.sync.aligned.m8n8.x4.shared.b16 {%0,%1,%2,%3}, [%4];" \
        : "=r"(d0), "=r"(d1), "=r"(d2), "=r"(d3) : "r"(addr))

#define MMA16816(c, a, b) \
    asm volatile("mma.sync.aligned.m16n8k16.row.col.f32.bf16.bf16.f32 " \
        "{%0,%1,%2,%3}, {%4,%5,%6,%7}, {%8,%9}, {%0,%1,%2,%3};" \
        : "+f"((c)[0]), "+f"((c)[1]), "+f"((c)[2]), "+f"((c)[3]) \
        : "r"((a)[0]), "r"((a)[1]), "r"((a)[2]), "r"((a)[3]), "r"((b)[0]), "r"((b)[1]))

// ---------------- scratch ----------------
__device__ float g_attn[HEADS * LL * LL];                        // fp32 logits/probs [h][l][k]
__device__ __nv_bfloat16 g_attn_bf[(size_t)HEADS * LL * LL];     // A bf16 [h][l][k]
__device__ __nv_bfloat16 g_vt_bf[(size_t)HEADS * NCC * LL];      // B bf16 [h][j][k]
__device__ float g_o [(size_t)HEADS * LL * NN * CHN];            // [h][l][n*C+c]
__device__ float g_tmid[(size_t)NT * DOUT];                      // [n*L+l][d]

// ---------------- K1: symmetrize + LayerNorm(128) + pair logits (i<=j only) ----------------
__global__ void k1_sym_ln_logits(const float* __restrict__ src,
                                 const float* __restrict__ Wp,
                                 const float* __restrict__ bp,
                                 const float* __restrict__ gn,
                                 const float* __restrict__ btn) {
    int lane = threadIdx.x & 31;
    int warp = (blockIdx.x * blockDim.x + threadIdx.x) >> 5;
    int nw   = (gridDim.x * blockDim.x) >> 5;
    int d0 = lane * 4;

    float gg[4], bb[4], wp[4][4], bph[4];
#pragma unroll
    for (int q = 0; q < 4; q++) { gg[q] = gn[d0 + q]; bb[q] = btn[d0 + q]; }
#pragma unroll
    for (int q = 0; q < 4; q++)
#pragma unroll
        for (int h = 0; h < 4; h++) wp[q][h] = Wp[(d0 + q) * 4 + h];
#pragma unroll
    for (int h = 0; h < 4; h++) bph[h] = bp[h];

    for (int p = warp; p < LL * LL; p += nw) {
        int i = p / LL, j = p - i * LL;
        if (i > j) continue;
        float4 a = *(const float4*)(src + ((size_t)i * LL + j) * DIN + d0);
        float4 b = *(const float4*)(src + ((size_t)j * LL + i) * DIN + d0);
        float s[4];
        s[0] = 0.5f * (a.x + b.x); s[1] = 0.5f * (a.y + b.y);
        s[2] = 0.5f * (a.z + b.z); s[3] = 0.5f * (a.w + b.w);

        float m = s[0] + s[1] + s[2] + s[3];
#pragma unroll
        for (int o = 16; o > 0; o >>= 1) m += __shfl_xor_sync(~0u, m, o);
        m *= (1.0f / 128.0f);

        float dv[4], var = 0.f;
#pragma unroll
        for (int q = 0; q < 4; q++) { dv[q] = s[q] - m; var += dv[q] * dv[q]; }
#pragma unroll
        for (int o = 16; o > 0; o >>= 1) var += __shfl_xor_sync(~0u, var, o);
        float inv = rsqrtf(var * (1.0f / 128.0f) + EPSV);

        float lg[4] = {0.f, 0.f, 0.f, 0.f};
#pragma unroll
        for (int q = 0; q < 4; q++) {
            float y = gg[q] * dv[q] * inv + bb[q];
#pragma unroll
            for (int h = 0; h < 4; h++) lg[h] += y * wp[q][h];
        }
#pragma unroll
        for (int h = 0; h < 4; h++)
#pragma unroll
            for (int o = 16; o > 0; o >>= 1) lg[h] += __shfl_xor_sync(~0u, lg[h], o);

        if (lane == 0) {
#pragma unroll
            for (int h = 0; h < 4; h++) {
                float v = lg[h] + bph[h];
                g_attn[h * LL * LL + j * LL + i] = v;
                g_attn[h * LL * LL + i * LL + j] = v;
            }
        }
    }
}

// ---------------- K2: softmax over k; emit fp32 (unused downstream) + bf16 A ----------------
__global__ void k2_softmax() {
    int lane = threadIdx.x & 31;
    int row  = (blockIdx.x * blockDim.x + threadIdx.x) >> 5;
    if (row >= HEADS * LL) return;
    const float* p = g_attn + (size_t)row * LL;
    float x[12];
    float mx = -1e30f;
#pragma unroll
    for (int q = 0; q < 12; q++) { x[q] = p[lane + q * 32]; mx = fmaxf(mx, x[q]); }
#pragma unroll
    for (int o = 16; o > 0; o >>= 1) mx = fmaxf(mx, __shfl_xor_sync(~0u, mx, o));
    float s = 0.f;
#pragma unroll
    for (int q = 0; q < 12; q++) { x[q] = __expf(x[q] - mx); s += x[q]; }
#pragma unroll
    for (int o = 16; o > 0; o >>= 1) s += __shfl_xor_sync(~0u, s, o);
    float rr = 1.0f / s;

    __nv_bfloat16* arow = g_attn_bf + (size_t)row * LL;
#pragma unroll
    for (int q = 0; q < 12; q++)
        arow[lane + q * 32] = __float2bfloat16_rn(x[q] * rr);
}

// ---------------- K3: v = LN(tgt) @ Wm + bm -> bf16 B [h][j][k] ----------------
__global__ void __launch_bounds__(256) k3_vproj(const float* __restrict__ tgt,
                                                const float* __restrict__ Wm,
                                                const float* __restrict__ bm,
                                                const float* __restrict__ g1,
                                                const float* __restrict__ bt1) {
    extern __shared__ float sm3[];
    float* Xs = sm3;             // [64][132]
    float* Ws = sm3 + 64 * 132;  // [64][64]
    int tid = threadIdx.x;
    for (int idx = tid; idx < 4096; idx += 256) Ws[idx] = Wm[idx];

    int lane = tid & 31, w = tid >> 5;
    int t0 = blockIdx.x * 128;
    float g1a = g1[lane * 2], g1b = g1[lane * 2 + 1];
    float ba = bt1[lane * 2], bb = bt1[lane * 2 + 1];
#pragma unroll 4
    for (int s = 0; s < 16; s++) {
        int tt = w * 16 + s;
        float2 x = *(const float2*)(tgt + (size_t)(t0 + tt) * 64 + lane * 2);
        float m = x.x + x.y;
#pragma unroll
        for (int o = 16; o > 0; o >>= 1) m += __shfl_xor_sync(~0u, m, o);
        m *= (1.0f / 64.0f);
        float dx0 = x.x - m, dx1 = x.y - m;
        float v = dx0 * dx0 + dx1 * dx1;
#pragma unroll
        for (int o = 16; o > 0; o >>= 1) v += __shfl_xor_sync(~0u, v, o);
        float inv = rsqrtf(v * (1.0f / 64.0f) + EPSV);
        Xs[(2 * lane) * 132 + tt]     = g1a * dx0 * inv + ba;
        Xs[(2 * lane + 1) * 132 + tt] = g1b * dx1 * inv + bb;
    }
    __syncthreads();

    int tx = tid & 15, ty = tid >> 4;
    float4 bmv = *(const float4*)(bm + tx * 4);
    u64t acc2[4][4];
#pragma unroll
    for (int rp = 0; rp < 4; rp++) {
        acc2[rp][0] = dup2(bmv.x); acc2[rp][1] = dup2(bmv.y);
        acc2[rp][2] = dup2(bmv.z); acc2[rp][3] = dup2(bmv.w);
    }
#pragma unroll 8
    for (int i = 0; i < 64; i++) {
        const u64t* ap = (const u64t*)&Xs[i * 132 + ty * 8];
        float4 bw = *(const float4*)&Ws[i * 64 + tx * 4];
        u64t bd0 = dup2(bw.x), bd1 = dup2(bw.y), bd2 = dup2(bw.z), bd3 = dup2(bw.w);
#pragma unroll
        for (int rp = 0; rp < 4; rp++) {
            u64t a2 = ap[rp];
            ffma2(acc2[rp][0], a2, bd0);
            ffma2(acc2[rp][1], a2, bd1);
            ffma2(acc2[rp][2], a2, bd2);
            ffma2(acc2[rp][3], a2, bd3);
        }
    }
    // col e = tx*4+jj -> head jj, channel tx; B row j = n*16+tx; k pair = tokens
    int n = blockIdx.x / 3;
    int kbase = (blockIdx.x % 3) * 128 + ty * 8;
#pragma unroll
    for (int rp = 0; rp < 4; rp++) {
        int k = kbase + rp * 2;
#pragma unroll
        for (int jj = 0; jj < 4; jj++) {
            float2 v = unpack2(acc2[rp][jj]);
            uint32_t pk = ((uint32_t)__bfloat16_as_ushort(__float2bfloat16_rn(v.y)) << 16)
                        |  (uint32_t)__bfloat16_as_ushort(__float2bfloat16_rn(v.x));
            size_t idx = ((size_t)jj * NCC + n * 16 + tx) * LL + k;
            *(uint32_t*)&g_vt_bf[idx] = pk;
        }
    }
}

// ---------------- K4: HMMA bf16 GEMM  C[h][l][j] = attn[h][l][k] * v[h][j][k]^T ----------------
// block 128x128, BK=64, 8 warps (wm 2 x wn 4), warp tile m64 x n32
#define K4_STR 72
#define K4_BUF (128 * K4_STR)
#define K4_SMEM (4 * K4_BUF * 2)   /* 2 bufs x (A+B) x bf16 = 73728 B */
__global__ void __launch_bounds__(256) k4_hmma() {
    extern __shared__ __nv_bfloat16 smbf[];
    __nv_bfloat16* As = smbf;              // [2][128][72]
    __nv_bfloat16* Bs = smbf + 2 * K4_BUF; // [2][128][72]
    int h = blockIdx.z, l0 = blockIdx.y * 128, j0 = blockIdx.x * 128;
    const __nv_bfloat16* A = g_attn_bf + ((size_t)h * LL + l0) * LL;
    const __nv_bfloat16* B = g_vt_bf + ((size_t)h * NCC + j0) * LL;

    int tid = threadIdx.x;
    int wid = tid >> 5, lane = tid & 31;
    int wm = wid & 1, wn = wid >> 1;
    uint32_t smA = smem_u32(As), smB = smem_u32(Bs);

    float acc[4][4][4];
#pragma unroll
    for (int mt = 0; mt < 4; mt++)
#pragma unroll
        for (int nt = 0; nt < 4; nt++)
#pragma unroll
            for (int q = 0; q < 4; q++) acc[mt][nt][q] = 0.f;

    int lrow = tid >> 3, lcg = tid & 7;          // load mapping: 32 rows/pass x 8 groups
    // prologue: k-tile 0 -> buf 0
#pragma unroll
    for (int r = 0; r < 4; r++) {
        int row = lrow + r * 32;
        uint32_t so = (uint32_t)(row * K4_STR + lcg * 8) * 2;
        cp_async16(smA + so, A + (size_t)row * LL + lcg * 8);
        cp_async16(smB + so, B + (size_t)row * LL + lcg * 8);
    }
    CP_COMMIT();
    CP_WAIT0();
    __syncthreads();

    int mat = lane >> 3, mr = lane & 7;
    for (int t = 0; t < 6; t++) {
        int cur = t & 1;
        if (t < 5) {
            int k0 = (t + 1) * 64;
            uint32_t bo = (uint32_t)(cur ^ 1) * K4_BUF * 2;
#pragma unroll
            for (int r = 0; r < 4; r++) {
                int row = lrow + r * 32;
                uint32_t so = bo + (uint32_t)(row * K4_STR + lcg * 8) * 2;
                cp_async16(smA + so, A + (size_t)row * LL + k0 + lcg * 8);
                cp_async16(smB + so, B + (size_t)row * LL + k0 + lcg * 8);
            }
            CP_COMMIT();
        }
        uint32_t baseA = smA + (uint32_t)cur * K4_BUF * 2;
        uint32_t baseB = smB + (uint32_t)cur * K4_BUF * 2;
#pragma unroll
        for (int kk = 0; kk < 4; kk++) {
            uint32_t af[4][4], bf[4][2];
#pragma unroll
            for (int mt = 0; mt < 4; mt++) {
                int arow = wm * 64 + mt * 16 + (mat & 1) * 8 + mr;
                int acol = kk * 16 + (mat >> 1) * 8;
                LDMX4(af[mt][0], af[mt][1], af[mt][2], af[mt][3],
                      baseA + (uint32_t)(arow * K4_STR + acol) * 2);
            }
#pragma unroll
            for (int bt = 0; bt < 2; bt++) {
                int brow = wn * 32 + bt * 16 + (mat >> 1) * 8 + mr;
                int bcol = kk * 16 + (mat & 1) * 8;
                uint32_t r0, r1, r2, r3;
                LDMX4(r0, r1, r2, r3, baseB + (uint32_t)(brow * K4_STR + bcol) * 2);
                bf[bt * 2][0] = r0; bf[bt * 2][1] = r1;
                bf[bt * 2 + 1][0] = r2; bf[bt * 2 + 1][1] = r3;
            }
#pragma unroll
            for (int mt = 0; mt < 4; mt++)
#pragma unroll
                for (int nt = 0; nt < 4; nt++)
                    MMA16816(acc[mt][nt], af[mt], bf[nt]);
        }
        if (t < 5) CP_WAIT0();
        __syncthreads();
    }

    // epilogue: c0,c1 -> (r, n0..n0+1); c2,c3 -> (r+8, ...)
    int cr = lane >> 2, cn = (lane & 3) * 2;
#pragma unroll
    for (int mt = 0; mt < 4; mt++) {
        int m = l0 + wm * 64 + mt * 16 + cr;
        float* p0 = g_o + ((size_t)h * LL + m) * NCC + j0 + wn * 32 + cn;
        float* p1 = p0 + 8 * NCC;
#pragma unroll
        for (int nt = 0; nt < 4; nt++) {
            *(float2*)(p0 + nt * 8) = make_float2(acc[mt][nt][0], acc[mt][nt][1]);
            *(float2*)(p1 + nt * 8) = make_float2(acc[mt][nt][2], acc[mt][nt][3]);
        }
    }
}

// ---------------- K5: tmid = tgt + gather(g_o) @ Wo + bo (FFMA2) ----------------
__global__ void __launch_bounds__(256) k5_oproj(const float* __restrict__ tgt,
                                                const float* __restrict__ Wo,
                                                const float* __restrict__ bo) {
    extern __shared__ float sm5[];
    float* Xs = sm5;             // [64][132]  Xs[e][t]
    float* Ws = sm5 + 64 * 132;  // [64][64]
    int tid = threadIdx.x;
    for (int idx = tid; idx < 4096; idx += 256) Ws[idx] = Wo[idx];

    int t0 = blockIdx.x * 128;
    int n = blockIdx.x / 3;
    int lbase = (blockIdx.x % 3) * 128;

    {
        int c4 = tid & 3, hh = (tid >> 2) & 3, tg = tid >> 4;
#pragma unroll
        for (int p = 0; p < 8; p++) {
            int tt = p * 16 + tg;
            int l = lbase + tt;
            float4 v = *(const float4*)(g_o + (((size_t)hh * LL + l) * NN + n) * CHN + c4 * 4);
            int e0 = (c4 * 4) * 4 + hh;
            Xs[(e0 + 0) * 132 + tt] = v.x;
            Xs[(e0 + 4) * 132 + tt] = v.y;
            Xs[(e0 + 8) * 132 + tt] = v.z;
            Xs[(e0 + 12) * 132 + tt] = v.w;
        }
    }
    __syncthreads();

    int tx = tid & 15, ty = tid >> 4;
    float4 bov = *(const float4*)(bo + tx * 4);
    u64t acc2[4][4];
#pragma unroll
    for (int rp = 0; rp < 4; rp++) {
        acc2[rp][0] = dup2(bov.x); acc2[rp][1] = dup2(bov.y);
        acc2[rp][2] = dup2(bov.z); acc2[rp][3] = dup2(bov.w);
    }
#pragma unroll 8
    for (int i = 0; i < 64; i++) {
        const u64t* ap = (const u64t*)&Xs[i * 132 + ty * 8];
        float4 bw = *(const float4*)&Ws[i * 64 + tx * 4];
        u64t bd0 = dup2(bw.x), bd1 = dup2(bw.y), bd2 = dup2(bw.z), bd3 = dup2(bw.w);
#pragma unroll
        for (int rp = 0; rp < 4; rp++) {
            u64t a2 = ap[rp];
            ffma2(acc2[rp][0], a2, bd0);
            ffma2(acc2[rp][1], a2, bd1);
            ffma2(acc2[rp][2], a2, bd2);
            ffma2(acc2[rp][3], a2, bd3);
        }
    }
#pragma unroll
    for (int rp = 0; rp < 4; rp++) {
        int t = t0 + ty * 8 + rp * 2;
        float2 v0 = unpack2(acc2[rp][0]);
        float2 v1 = unpack2(acc2[rp][1]);
        float2 v2 = unpack2(acc2[rp][2]);
        float2 v3 = unpack2(acc2[rp][3]);
        float4 r0 = *(const float4*)(tgt + (size_t)t * 64 + tx * 4);
        float4 r1 = *(const float4*)(tgt + (size_t)(t + 1) * 64 + tx * 4);
        *(float4*)(g_tmid + (size_t)t * 64 + tx * 4) =
            make_float4(r0.x + v0.x, r0.y + v1.x, r0.z + v2.x, r0.w + v3.x);
        *(float4*)(g_tmid + (size_t)(t + 1) * 64 + tx * 4) =
            make_float4(r1.x + v0.y, r1.y + v1.y, r1.z + v2.y, r1.w + v3.y);
    }
}

// ---------------- K6: fused FFN, hidden in 2 chunks of 128, swizzled Hs ----------------
__global__ void __launch_bounds__(256, 1) k6_ffn(const float* __restrict__ W1,
                                                 const float* __restrict__ b1,
                                                 const float* __restrict__ W2,
                                                 const float* __restrict__ b2,
                                                 const float* __restrict__ g2,
                                                 const float* __restrict__ bt2,
                                                 float* __restrict__ out) {
    extern __shared__ float sm6[];
    float* Xn  = sm6;                  // [64][132]
    float* Hs  = Xn + 64 * 132;        // [128][132] (column-swizzled)
    float* W1c = Hs + 128 * 132;       // [64][128]
    float* W2c = W1c + 64 * 128;       // [128][64]
    int tid = threadIdx.x;
    int lane = tid & 31, w = tid >> 5;
    int t0 = blockIdx.x * 128;

    float g2a = g2[lane * 2], g2b = g2[lane * 2 + 1];
    float ba = bt2[lane * 2], bb = bt2[lane * 2 + 1];
#pragma unroll 4
    for (int s = 0; s < 16; s++) {
        int tt = w * 16 + s;
        float2 x = *(const float2*)(g_tmid + (size_t)(t0 + tt) * 64 + lane * 2);
        float m = x.x + x.y;
#pragma unroll
        for (int o = 16; o > 0; o >>= 1) m += __shfl_xor_sync(~0u, m, o);
        m *= (1.0f / 64.0f);
        float dx0 = x.x - m, dx1 = x.y - m;
        float v = dx0 * dx0 + dx1 * dx1;
#pragma unroll
        for (int o = 16; o > 0; o >>= 1) v += __shfl_xor_sync(~0u, v, o);
        float inv = rsqrtf(v * (1.0f / 64.0f) + EPSV);
        Xn[(2 * lane) * 132 + tt]     = g2a * dx0 * inv + ba;
        Xn[(2 * lane + 1) * 132 + tt] = g2b * dx1 * inv + bb;
    }

    int tx = tid & 15, ty = tid >> 4;
    u64t acc2[4][4];
#pragma unroll
    for (int rp = 0; rp < 4; rp++)
#pragma unroll
        for (int j = 0; j < 4; j++) acc2[rp][j] = 0ull;

    for (int step = 0; step < 2; step++) {
        int hbase = step * 128;
#pragma unroll
        for (int p = 0; p < 8; p++) {
            int f = tid + p * 256;
            int row = f >> 5;
            int c4 = (f & 31) * 4;
            *(float4*)&W1c[row * 128 + c4] = *(const float4*)(W1 + row * 256 + hbase + c4);
        }
#pragma unroll
        for (int p = 0; p < 8; p++) {
            int f = (tid + p * 256) * 4;
            *(float4*)&W2c[f] = *(const float4*)(W2 + hbase * 64 + f);
        }
        __syncthreads();

        float4 b10 = *(const float4*)(b1 + hbase + tx * 8);
        float4 b11 = *(const float4*)(b1 + hbase + tx * 8 + 4);
        u64t h2[4][8];
#pragma unroll
        for (int rp = 0; rp < 4; rp++) {
            h2[rp][0] = dup2(b10.x); h2[rp][1] = dup2(b10.y);
            h2[rp][2] = dup2(b10.z); h2[rp][3] = dup2(b10.w);
            h2[rp][4] = dup2(b11.x); h2[rp][5] = dup2(b11.y);
            h2[rp][6] = dup2(b11.z); h2[rp][7] = dup2(b11.w);
        }
#pragma unroll 8
        for (int i = 0; i < 64; i++) {
            const u64t* ap = (const u64t*)&Xn[i * 132 + ty * 8];
            float4 bw0 = *(const float4*)&W1c[i * 128 + tx * 8];
            float4 bw1 = *(const float4*)&W1c[i * 128 + tx * 8 + 4];
            u64t bd[8];
            bd[0] = dup2(bw0.x); bd[1] = dup2(bw0.y); bd[2] = dup2(bw0.z); bd[3] = dup2(bw0.w);
            bd[4] = dup2(bw1.x); bd[5] = dup2(bw1.y); bd[6] = dup2(bw1.z); bd[7] = dup2(bw1.w);
#pragma unroll
            for (int rp = 0; rp < 4; rp++) {
                u64t a2 = ap[rp];
#pragma unroll
                for (int j = 0; j < 8; j++) ffma2(h2[rp][j], a2, bd[j]);
            }
        }
#pragma unroll
        for (int rp = 0; rp < 4; rp++)
#pragma unroll
            for (int j = 0; j < 8; j++) {
                float2 v = unpack2(h2[rp][j]);
                v.x = fmaxf(v.x, 0.f);
                v.y = fmaxf(v.y, 0.f);
                *(float2*)&Hs[(tx * 8 + j) * 132 + ((ty ^ tx) * 8 + rp * 2)] = v;
            }
        __syncthreads();

#pragma unroll 8
        for (int f = 0; f < 128; f++) {
            int u = (f >> 3) & 15;
            const u64t* ap = (const u64t*)&Hs[f * 132 + ((ty ^ u) * 8)];
            float4 bw = *(const float4*)&W2c[f * 64 + tx * 4];
            u64t bd0 = dup2(bw.x), bd1 = dup2(bw.y), bd2 = dup2(bw.z), bd3 = dup2(bw.w);
#pragma unroll
            for (int rp = 0; rp < 4; rp++) {
                u64t a2 = ap[rp];
                ffma2(acc2[rp][0], a2, bd0);
                ffma2(acc2[rp][1], a2, bd1);
                ffma2(acc2[rp][2], a2, bd2);
                ffma2(acc2[rp][3], a2, bd3);
            }
        }
        __syncthreads();
    }

    float4 b2v = *(const float4*)(b2 + tx * 4);
#pragma unroll
    for (int rp = 0; rp < 4; rp++) {
        int t = t0 + ty * 8 + rp * 2;
        float4 r0 = *(const float4*)(g_tmid + (size_t)t * 64 + tx * 4);
        float4 r1 = *(const float4*)(g_tmid + (size_t)(t + 1) * 64 + tx * 4);
        float2 v0 = unpack2(acc2[rp][0]);
        float2 v1 = unpack2(acc2[rp][1]);
        float2 v2 = unpack2(acc2[rp][2]);
        float2 v3 = unpack2(acc2[rp][3]);
        *(float4*)(out + (size_t)t * 64 + tx * 4) = make_float4(
            r0.x + b2v.x + v0.x, r0.y + b2v.y + v1.x,
            r0.z + b2v.z + v2.x, r0.w + b2v.w + v3.x);
        *(float4*)(out + (size_t)(t + 1) * 64 + tx * 4) = make_float4(
            r1.x + b2v.x + v0.y, r1.y + b2v.y + v1.y,
            r1.z + b2v.z + v2.y, r1.w + b2v.w + v3.y);
    }
}

// ---------------- launch ----------------
#define SM3_BYTES ((64 * 132 + 64 * 64) * 4)
#define SM6_BYTES ((64 * 132 + 128 * 132 + 64 * 128 + 128 * 64) * 4)

extern "C" void kernel_launch(void* const* d_in, const int* in_sizes, int n_in,
                              void* d_out, int out_size) {
    (void)in_sizes; (void)n_in; (void)out_size;
    const float* src  = (const float*)d_in[0];
    const float* tgt  = (const float*)d_in[1];
    const float* Wp   = (const float*)d_in[2];
    const float* bp   = (const float*)d_in[3];
    const float* Wm   = (const float*)d_in[4];
    const float* bm   = (const float*)d_in[5];
    const float* Wo   = (const float*)d_in[6];
    const float* bo   = (const float*)d_in[7];
    const float* W1   = (const float*)d_in[8];
    const float* b1   = (const float*)d_in[9];
    const float* W2   = (const float*)d_in[10];
    const float* b2   = (const float*)d_in[11];
    const float* gn   = (const float*)d_in[12];
    const float* btn  = (const float*)d_in[13];
    const float* g1   = (const float*)d_in[14];
    const float* bt1  = (const float*)d_in[15];
    const float* g2   = (const float*)d_in[16];
    const float* bt2  = (const float*)d_in[17];
    float* out = (float*)d_out;

    static bool inited = false;
    if (!inited) {
        cudaFuncSetAttribute(k3_vproj, cudaFuncAttributeMaxDynamicSharedMemorySize, SM3_BYTES);
        cudaFuncSetAttribute(k4_hmma,  cudaFuncAttributeMaxDynamicSharedMemorySize, K4_SMEM);
        cudaFuncSetAttribute(k5_oproj, cudaFuncAttributeMaxDynamicSharedMemorySize, SM3_BYTES);
        cudaFuncSetAttribute(k6_ffn,   cudaFuncAttributeMaxDynamicSharedMemorySize, SM6_BYTES);
        inited = true;
    }

    k1_sym_ln_logits<<<4608, 256>>>(src, Wp, bp, gn, btn);
    k2_softmax<<<(HEADS * LL + 7) / 8, 256>>>();
    k3_vproj<<<NT / 128, 256, SM3_BYTES>>>(tgt, Wm, bm, g1, bt1);
    k4_hmma<<<dim3(NCC / 128, LL / 128, HEADS), 256, K4_SMEM>>>();
    k5_oproj<<<NT / 128, 256, SM3_BYTES>>>(tgt, Wo, bo);
    k6_ffn<<<NT / 128, 256, SM6_BYTES>>>(W1, b1, W2, b2, g2, bt2, out);
}

// round 16
// speedup vs baseline: 5.4524x; 1.5456x over previous
#include <cuda_runtime.h>
#include <cuda_bf16.h>
#include <cstdint>

#define LL 384
#define NN 512
#define DIN 128
#define DOUT 64
#define HEADS 4
#define CHN 16
#define DFF 256
#define NCC (NN*CHN)       /* 8192 */
#define NT (NN*LL)         /* 196608 */
#define EPSV 1e-5f

typedef unsigned long long u64t;

__device__ __forceinline__ u64t dup2(float v) {
    u64t r; asm("mov.b64 %0, {%1, %1};" : "=l"(r) : "f"(v)); return r;
}
__device__ __forceinline__ void ffma2(u64t &d, u64t a, u64t b) {
    asm("fma.rn.f32x2 %0, %1, %2, %0;" : "+l"(d) : "l"(a), "l"(b));
}
__device__ __forceinline__ float2 unpack2(u64t v) {
    float2 f; asm("mov.b64 {%0, %1}, %2;" : "=f"(f.x), "=f"(f.y) : "l"(v)); return f;
}
__device__ __forceinline__ uint32_t smem_u32(const void* p) {
    uint32_t a;
    asm("{ .reg .u64 t; cvta.to.shared.u64 t, %1; cvt.u32.u64 %0, t; }" : "=r"(a) : "l"(p));
    return a;
}
__device__ __forceinline__ void cp_async16(uint32_t s, const void* g) {
    asm volatile("cp.async.cg.shared.global [%0], [%1], 16;" :: "r"(s), "l"(g));
}
#define CP_COMMIT() asm volatile("cp.async.commit_group;" ::: "memory")
#define CP_WAIT0()  asm volatile("cp.async.wait_group 0;" ::: "memory")

#define LDMX4(d0, d1, d2, d3, addr) \
    asm volatile("ldmatrix.sync.aligned.m8n8.x4.shared.b16 {%0,%1,%2,%3}, [%4];" \
        : "=r"(d0), "=r"(d1), "=r"(d2), "=r"(d3) : "r"(addr))

#define MMA16816(c, a, b) \
    asm volatile("mma.sync.aligned.m16n8k16.row.col.f32.bf16.bf16.f32 " \
        "{%0,%1,%2,%3}, {%4,%5,%6,%7}, {%8,%9}, {%0,%1,%2,%3};" \
        : "+f"((c)[0]), "+f"((c)[1]), "+f"((c)[2]), "+f"((c)[3]) \
        : "r"((a)[0]), "r"((a)[1]), "r"((a)[2]), "r"((a)[3]), "r"((b)[0]), "r"((b)[1]))

__device__ __forceinline__ uint32_t packbf2(float x, float y) {
    return ((uint32_t)__bfloat16_as_ushort(__float2bfloat16_rn(y)) << 16)
         |  (uint32_t)__bfloat16_as_ushort(__float2bfloat16_rn(x));
}

// ---------------- scratch ----------------
__device__ float g_attn[HEADS * LL * LL];                        // fp32 logits [h][l][k]
__device__ __nv_bfloat16 g_attn_bf[(size_t)HEADS * LL * LL];     // A bf16 [h][l][k]
__device__ __nv_bfloat16 g_vt_bf[(size_t)HEADS * NCC * LL];      // B bf16 [h][j][k]
__device__ float g_o [(size_t)HEADS * LL * NN * CHN];            // [h][l][n*C+c]
__device__ float g_tmid[(size_t)NT * DOUT];                      // [n*L+l][d]
__device__ __nv_bfloat16 g_W1bf[DFF * DOUT];                     // [256 hid][64 in]
__device__ __nv_bfloat16 g_W2bf[DOUT * DFF];                     // [64 out][256 hid]

// ---------------- K0: weight transpose+convert (once per launch) ----------------
__global__ void k0_wconv(const float* __restrict__ W1, const float* __restrict__ W2) {
    int t = blockIdx.x * 256 + threadIdx.x;
    int stride = gridDim.x * 256;
    for (int i = t; i < DFF * DOUT; i += stride) {
        int n = i >> 6, k = i & 63;
        g_W1bf[i] = __float2bfloat16_rn(W1[k * DFF + n]);
    }
    for (int i = t; i < DOUT * DFF; i += stride) {
        int n = i >> 8, k = i & 255;
        g_W2bf[i] = __float2bfloat16_rn(W2[k * DOUT + n]);
    }
}

// ---------------- K1: symmetrize + LayerNorm(128) + pair logits (i<=j only) ----------------
__global__ void k1_sym_ln_logits(const float* __restrict__ src,
                                 const float* __restrict__ Wp,
                                 const float* __restrict__ bp,
                                 const float* __restrict__ gn,
                                 const float* __restrict__ btn) {
    int lane = threadIdx.x & 31;
    int warp = (blockIdx.x * blockDim.x + threadIdx.x) >> 5;
    int nw   = (gridDim.x * blockDim.x) >> 5;
    int d0 = lane * 4;

    float gg[4], bb[4], wp[4][4], bph[4];
#pragma unroll
    for (int q = 0; q < 4; q++) { gg[q] = gn[d0 + q]; bb[q] = btn[d0 + q]; }
#pragma unroll
    for (int q = 0; q < 4; q++)
#pragma unroll
        for (int h = 0; h < 4; h++) wp[q][h] = Wp[(d0 + q) * 4 + h];
#pragma unroll
    for (int h = 0; h < 4; h++) bph[h] = bp[h];

    for (int p = warp; p < LL * LL; p += nw) {
        int i = p / LL, j = p - i * LL;
        if (i > j) continue;
        float4 a = *(const float4*)(src + ((size_t)i * LL + j) * DIN + d0);
        float4 b = *(const float4*)(src + ((size_t)j * LL + i) * DIN + d0);
        float s[4];
        s[0] = 0.5f * (a.x + b.x); s[1] = 0.5f * (a.y + b.y);
        s[2] = 0.5f * (a.z + b.z); s[3] = 0.5f * (a.w + b.w);

        float m = s[0] + s[1] + s[2] + s[3];
#pragma unroll
        for (int o = 16; o > 0; o >>= 1) m += __shfl_xor_sync(~0u, m, o);
        m *= (1.0f / 128.0f);

        float dv[4], var = 0.f;
#pragma unroll
        for (int q = 0; q < 4; q++) { dv[q] = s[q] - m; var += dv[q] * dv[q]; }
#pragma unroll
        for (int o = 16; o > 0; o >>= 1) var += __shfl_xor_sync(~0u, var, o);
        float inv = rsqrtf(var * (1.0f / 128.0f) + EPSV);

        float lg[4] = {0.f, 0.f, 0.f, 0.f};
#pragma unroll
        for (int q = 0; q < 4; q++) {
            float y = gg[q] * dv[q] * inv + bb[q];
#pragma unroll
            for (int h = 0; h < 4; h++) lg[h] += y * wp[q][h];
        }
#pragma unroll
        for (int h = 0; h < 4; h++)
#pragma unroll
            for (int o = 16; o > 0; o >>= 1) lg[h] += __shfl_xor_sync(~0u, lg[h], o);

        if (lane == 0) {
#pragma unroll
            for (int h = 0; h < 4; h++) {
                float v = lg[h] + bph[h];
                g_attn[h * LL * LL + j * LL + i] = v;
                g_attn[h * LL * LL + i * LL + j] = v;
            }
        }
    }
}

// ---------------- K2: softmax over k; emit bf16 A ----------------
__global__ void k2_softmax() {
    int lane = threadIdx.x & 31;
    int row  = (blockIdx.x * blockDim.x + threadIdx.x) >> 5;
    if (row >= HEADS * LL) return;
    const float* p = g_attn + (size_t)row * LL;
    float x[12];
    float mx = -1e30f;
#pragma unroll
    for (int q = 0; q < 12; q++) { x[q] = p[lane + q * 32]; mx = fmaxf(mx, x[q]); }
#pragma unroll
    for (int o = 16; o > 0; o >>= 1) mx = fmaxf(mx, __shfl_xor_sync(~0u, mx, o));
    float s = 0.f;
#pragma unroll
    for (int q = 0; q < 12; q++) { x[q] = __expf(x[q] - mx); s += x[q]; }
#pragma unroll
    for (int o = 16; o > 0; o >>= 1) s += __shfl_xor_sync(~0u, s, o);
    float rr = 1.0f / s;

    __nv_bfloat16* arow = g_attn_bf + (size_t)row * LL;
#pragma unroll
    for (int q = 0; q < 12; q++)
        arow[lane + q * 32] = __float2bfloat16_rn(x[q] * rr);
}

// ---------------- K3: v = LN(tgt) @ Wm + bm -> bf16 B [h][j][k] ----------------
__global__ void __launch_bounds__(256) k3_vproj(const float* __restrict__ tgt,
                                                const float* __restrict__ Wm,
                                                const float* __restrict__ bm,
                                                const float* __restrict__ g1,
                                                const float* __restrict__ bt1) {
    extern __shared__ float sm3[];
    float* Xs = sm3;             // [64][132]
    float* Ws = sm3 + 64 * 132;  // [64][64]
    int tid = threadIdx.x;
    for (int idx = tid; idx < 4096; idx += 256) Ws[idx] = Wm[idx];

    int lane = tid & 31, w = tid >> 5;
    int t0 = blockIdx.x * 128;
    float g1a = g1[lane * 2], g1b = g1[lane * 2 + 1];
    float ba = bt1[lane * 2], bb = bt1[lane * 2 + 1];
#pragma unroll 4
    for (int s = 0; s < 16; s++) {
        int tt = w * 16 + s;
        float2 x = *(const float2*)(tgt + (size_t)(t0 + tt) * 64 + lane * 2);
        float m = x.x + x.y;
#pragma unroll
        for (int o = 16; o > 0; o >>= 1) m += __shfl_xor_sync(~0u, m, o);
        m *= (1.0f / 64.0f);
        float dx0 = x.x - m, dx1 = x.y - m;
        float v = dx0 * dx0 + dx1 * dx1;
#pragma unroll
        for (int o = 16; o > 0; o >>= 1) v += __shfl_xor_sync(~0u, v, o);
        float inv = rsqrtf(v * (1.0f / 64.0f) + EPSV);
        Xs[(2 * lane) * 132 + tt]     = g1a * dx0 * inv + ba;
        Xs[(2 * lane + 1) * 132 + tt] = g1b * dx1 * inv + bb;
    }
    __syncthreads();

    int tx = tid & 15, ty = tid >> 4;
    float4 bmv = *(const float4*)(bm + tx * 4);
    u64t acc2[4][4];
#pragma unroll
    for (int rp = 0; rp < 4; rp++) {
        acc2[rp][0] = dup2(bmv.x); acc2[rp][1] = dup2(bmv.y);
        acc2[rp][2] = dup2(bmv.z); acc2[rp][3] = dup2(bmv.w);
    }
#pragma unroll 8
    for (int i = 0; i < 64; i++) {
        const u64t* ap = (const u64t*)&Xs[i * 132 + ty * 8];
        float4 bw = *(const float4*)&Ws[i * 64 + tx * 4];
        u64t bd0 = dup2(bw.x), bd1 = dup2(bw.y), bd2 = dup2(bw.z), bd3 = dup2(bw.w);
#pragma unroll
        for (int rp = 0; rp < 4; rp++) {
            u64t a2 = ap[rp];
            ffma2(acc2[rp][0], a2, bd0);
            ffma2(acc2[rp][1], a2, bd1);
            ffma2(acc2[rp][2], a2, bd2);
            ffma2(acc2[rp][3], a2, bd3);
        }
    }
    int n = blockIdx.x / 3;
    int kbase = (blockIdx.x % 3) * 128 + ty * 8;
#pragma unroll
    for (int rp = 0; rp < 4; rp++) {
        int k = kbase + rp * 2;
#pragma unroll
        for (int jj = 0; jj < 4; jj++) {
            float2 v = unpack2(acc2[rp][jj]);
            size_t idx = ((size_t)jj * NCC + n * 16 + tx) * LL + k;
            *(uint32_t*)&g_vt_bf[idx] = packbf2(v.x, v.y);
        }
    }
}

// ---------------- K4: HMMA bf16 GEMM  C[h][l][j] = attn[h][l][k] * v[h][j][k]^T ----------------
#define K4_STR 72
#define K4_BUF (128 * K4_STR)
#define K4_SMEM (4 * K4_BUF * 2)
__global__ void __launch_bounds__(256) k4_hmma() {
    extern __shared__ __nv_bfloat16 smbf[];
    __nv_bfloat16* As = smbf;
    __nv_bfloat16* Bs = smbf + 2 * K4_BUF;
    int h = blockIdx.z, l0 = blockIdx.y * 128, j0 = blockIdx.x * 128;
    const __nv_bfloat16* A = g_attn_bf + ((size_t)h * LL + l0) * LL;
    const __nv_bfloat16* B = g_vt_bf + ((size_t)h * NCC + j0) * LL;

    int tid = threadIdx.x;
    int wid = tid >> 5, lane = tid & 31;
    int wm = wid & 1, wn = wid >> 1;
    uint32_t smA = smem_u32(As), smB = smem_u32(Bs);

    float acc[4][4][4];
#pragma unroll
    for (int mt = 0; mt < 4; mt++)
#pragma unroll
        for (int nt = 0; nt < 4; nt++)
#pragma unroll
            for (int q = 0; q < 4; q++) acc[mt][nt][q] = 0.f;

    int lrow = tid >> 3, lcg = tid & 7;
#pragma unroll
    for (int r = 0; r < 4; r++) {
        int row = lrow + r * 32;
        uint32_t so = (uint32_t)(row * K4_STR + lcg * 8) * 2;
        cp_async16(smA + so, A + (size_t)row * LL + lcg * 8);
        cp_async16(smB + so, B + (size_t)row * LL + lcg * 8);
    }
    CP_COMMIT();
    CP_WAIT0();
    __syncthreads();

    int mat = lane >> 3, mr = lane & 7;
    for (int t = 0; t < 6; t++) {
        int cur = t & 1;
        if (t < 5) {
            int k0 = (t + 1) * 64;
            uint32_t bo = (uint32_t)(cur ^ 1) * K4_BUF * 2;
#pragma unroll
            for (int r = 0; r < 4; r++) {
                int row = lrow + r * 32;
                uint32_t so = bo + (uint32_t)(row * K4_STR + lcg * 8) * 2;
                cp_async16(smA + so, A + (size_t)row * LL + k0 + lcg * 8);
                cp_async16(smB + so, B + (size_t)row * LL + k0 + lcg * 8);
            }
            CP_COMMIT();
        }
        uint32_t baseA = smA + (uint32_t)cur * K4_BUF * 2;
        uint32_t baseB = smB + (uint32_t)cur * K4_BUF * 2;
#pragma unroll
        for (int kk = 0; kk < 4; kk++) {
            uint32_t af[4][4], bf[4][2];
#pragma unroll
            for (int mt = 0; mt < 4; mt++) {
                int arow = wm * 64 + mt * 16 + (mat & 1) * 8 + mr;
                int acol = kk * 16 + (mat >> 1) * 8;
                LDMX4(af[mt][0], af[mt][1], af[mt][2], af[mt][3],
                      baseA + (uint32_t)(arow * K4_STR + acol) * 2);
            }
#pragma unroll
            for (int bt = 0; bt < 2; bt++) {
                int brow = wn * 32 + bt * 16 + (mat >> 1) * 8 + mr;
                int bcol = kk * 16 + (mat & 1) * 8;
                uint32_t r0, r1, r2, r3;
                LDMX4(r0, r1, r2, r3, baseB + (uint32_t)(brow * K4_STR + bcol) * 2);
                bf[bt * 2][0] = r0; bf[bt * 2][1] = r1;
                bf[bt * 2 + 1][0] = r2; bf[bt * 2 + 1][1] = r3;
            }
#pragma unroll
            for (int mt = 0; mt < 4; mt++)
#pragma unroll
                for (int nt = 0; nt < 4; nt++)
                    MMA16816(acc[mt][nt], af[mt], bf[nt]);
        }
        if (t < 5) CP_WAIT0();
        __syncthreads();
    }

    int cr = lane >> 2, cn = (lane & 3) * 2;
#pragma unroll
    for (int mt = 0; mt < 4; mt++) {
        int m = l0 + wm * 64 + mt * 16 + cr;
        float* p0 = g_o + ((size_t)h * LL + m) * NCC + j0 + wn * 32 + cn;
        float* p1 = p0 + 8 * NCC;
#pragma unroll
        for (int nt = 0; nt < 4; nt++) {
            *(float2*)(p0 + nt * 8) = make_float2(acc[mt][nt][0], acc[mt][nt][1]);
            *(float2*)(p1 + nt * 8) = make_float2(acc[mt][nt][2], acc[mt][nt][3]);
        }
    }
}

// ---------------- K5: tmid = tgt + gather(g_o) @ Wo + bo (FFMA2) ----------------
__global__ void __launch_bounds__(256) k5_oproj(const float* __restrict__ tgt,
                                                const float* __restrict__ Wo,
                                                const float* __restrict__ bo) {
    extern __shared__ float sm5[];
    float* Xs = sm5;             // [64][132]
    float* Ws = sm5 + 64 * 132;  // [64][64]
    int tid = threadIdx.x;
    for (int idx = tid; idx < 4096; idx += 256) Ws[idx] = Wo[idx];

    int t0 = blockIdx.x * 128;
    int n = blockIdx.x / 3;
    int lbase = (blockIdx.x % 3) * 128;

    {
        int c4 = tid & 3, hh = (tid >> 2) & 3, tg = tid >> 4;
#pragma unroll
        for (int p = 0; p < 8; p++) {
            int tt = p * 16 + tg;
            int l = lbase + tt;
            float4 v = *(const float4*)(g_o + (((size_t)hh * LL + l) * NN + n) * CHN + c4 * 4);
            int e0 = (c4 * 4) * 4 + hh;
            Xs[(e0 + 0) * 132 + tt] = v.x;
            Xs[(e0 + 4) * 132 + tt] = v.y;
            Xs[(e0 + 8) * 132 + tt] = v.z;
            Xs[(e0 + 12) * 132 + tt] = v.w;
        }
    }
    __syncthreads();

    int tx = tid & 15, ty = tid >> 4;
    float4 bov = *(const float4*)(bo + tx * 4);
    u64t acc2[4][4];
#pragma unroll
    for (int rp = 0; rp < 4; rp++) {
        acc2[rp][0] = dup2(bov.x); acc2[rp][1] = dup2(bov.y);
        acc2[rp][2] = dup2(bov.z); acc2[rp][3] = dup2(bov.w);
    }
#pragma unroll 8
    for (int i = 0; i < 64; i++) {
        const u64t* ap = (const u64t*)&Xs[i * 132 + ty * 8];
        float4 bw = *(const float4*)&Ws[i * 64 + tx * 4];
        u64t bd0 = dup2(bw.x), bd1 = dup2(bw.y), bd2 = dup2(bw.z), bd3 = dup2(bw.w);
#pragma unroll
        for (int rp = 0; rp < 4; rp++) {
            u64t a2 = ap[rp];
            ffma2(acc2[rp][0], a2, bd0);
            ffma2(acc2[rp][1], a2, bd1);
            ffma2(acc2[rp][2], a2, bd2);
            ffma2(acc2[rp][3], a2, bd3);
        }
    }
#pragma unroll
    for (int rp = 0; rp < 4; rp++) {
        int t = t0 + ty * 8 + rp * 2;
        float2 v0 = unpack2(acc2[rp][0]);
        float2 v1 = unpack2(acc2[rp][1]);
        float2 v2 = unpack2(acc2[rp][2]);
        float2 v3 = unpack2(acc2[rp][3]);
        float4 r0 = *(const float4*)(tgt + (size_t)t * 64 + tx * 4);
        float4 r1 = *(const float4*)(tgt + (size_t)(t + 1) * 64 + tx * 4);
        *(float4*)(g_tmid + (size_t)t * 64 + tx * 4) =
            make_float4(r0.x + v0.x, r0.y + v1.x, r0.z + v2.x, r0.w + v3.x);
        *(float4*)(g_tmid + (size_t)(t + 1) * 64 + tx * 4) =
            make_float4(r1.x + v0.y, r1.y + v1.y, r1.z + v2.y, r1.w + v3.y);
    }
}

// ---------------- K6: HMMA FFN: out = tmid + relu(LN(tmid)@W1+b1)@W2+b2 ----------------
// smem: Xb[128][72]bf + W1b[256][72]bf + W2b[64][264]bf + H[128][264]bf + b1s[256] + b2s[64]
#define K6_XOFF 0
#define K6_W1OFF (128 * 72)
#define K6_W2OFF (K6_W1OFF + 256 * 72)
#define K6_HOFF  (K6_W2OFF + 64 * 264)
#define K6_BF_ELEMS (K6_HOFF + 128 * 264)
#define K6_SMEM (K6_BF_ELEMS * 2 + 256 * 4 + 64 * 4)
__global__ void __launch_bounds__(256, 1) k6_ffn_hmma(const float* __restrict__ b1,
                                                      const float* __restrict__ b2,
                                                      const float* __restrict__ g2,
                                                      const float* __restrict__ bt2,
                                                      float* __restrict__ out) {
    extern __shared__ __nv_bfloat16 sm6b[];
    __nv_bfloat16* Xb  = sm6b + K6_XOFF;
    __nv_bfloat16* W1b = sm6b + K6_W1OFF;
    __nv_bfloat16* W2b = sm6b + K6_W2OFF;
    __nv_bfloat16* Hb  = sm6b + K6_HOFF;
    float* b1s = (float*)(sm6b + K6_BF_ELEMS);
    float* b2s = b1s + 256;
    uint32_t sX = smem_u32(Xb), sW1 = smem_u32(W1b), sW2 = smem_u32(W2b), sH = smem_u32(Hb);

    int tid = threadIdx.x;
    int lane = tid & 31, w = tid >> 5;
    int t0 = blockIdx.x * 128;

    // stage weights (bf16, pre-transposed) via cp.async
#pragma unroll
    for (int i = 0; i < 8; i++) {
        int idx = tid + i * 256;            // 2048 chunks of 8 bf16
        int row = idx >> 3, ch = idx & 7;   // W1b [256][64->72]
        cp_async16(sW1 + (uint32_t)(row * 72 + ch * 8) * 2, g_W1bf + row * 64 + ch * 8);
    }
#pragma unroll
    for (int i = 0; i < 8; i++) {
        int idx = tid + i * 256;
        int row = idx >> 5, ch = idx & 31;  // W2b [64][256->264]
        cp_async16(sW2 + (uint32_t)(row * 264 + ch * 8) * 2, g_W2bf + row * 256 + ch * 8);
    }
    CP_COMMIT();
    b1s[tid] = b1[tid];
    if (tid < 64) b2s[tid] = b2[tid];

    // LN -> Xb bf16 [token][feat], stride 72
    float g2a = g2[lane * 2], g2b = g2[lane * 2 + 1];
    float ba = bt2[lane * 2], bb = bt2[lane * 2 + 1];
#pragma unroll 4
    for (int s = 0; s < 16; s++) {
        int tt = w * 16 + s;
        float2 x = *(const float2*)(g_tmid + (size_t)(t0 + tt) * 64 + lane * 2);
        float m = x.x + x.y;
#pragma unroll
        for (int o = 16; o > 0; o >>= 1) m += __shfl_xor_sync(~0u, m, o);
        m *= (1.0f / 64.0f);
        float dx0 = x.x - m, dx1 = x.y - m;
        float v = dx0 * dx0 + dx1 * dx1;
#pragma unroll
        for (int o = 16; o > 0; o >>= 1) v += __shfl_xor_sync(~0u, v, o);
        float inv = rsqrtf(v * (1.0f / 64.0f) + EPSV);
        *(uint32_t*)&Xb[tt * 72 + lane * 2] =
            packbf2(g2a * dx0 * inv + ba, g2b * dx1 * inv + bb);
    }
    CP_WAIT0();
    __syncthreads();

    int wid = tid >> 5;
    int wm = wid & 3, wn = wid >> 2;
    int mat = lane >> 3, mr = lane & 7;
    int cr = lane >> 2, cn = (lane & 3) * 2;

    // GEMM1: C[128 tok][256 hid] = Xb @ W1b^T, two n-passes of 128
#pragma unroll
    for (int np = 0; np < 2; np++) {
        float acc[2][8][4];
#pragma unroll
        for (int mt = 0; mt < 2; mt++)
#pragma unroll
            for (int nt = 0; nt < 8; nt++)
#pragma unroll
                for (int q = 0; q < 4; q++) acc[mt][nt][q] = 0.f;
        int nb = np * 128 + wn * 64;
#pragma unroll
        for (int kk = 0; kk < 4; kk++) {
            uint32_t af[2][4], bfr[8][2];
#pragma unroll
            for (int mt = 0; mt < 2; mt++) {
                int arow = wm * 32 + mt * 16 + (mat & 1) * 8 + mr;
                int acol = kk * 16 + (mat >> 1) * 8;
                LDMX4(af[mt][0], af[mt][1], af[mt][2], af[mt][3],
                      sX + (uint32_t)(arow * 72 + acol) * 2);
            }
#pragma unroll
            for (int bt = 0; bt < 4; bt++) {
                int brow = nb + bt * 16 + (mat >> 1) * 8 + mr;
                int bcol = kk * 16 + (mat & 1) * 8;
                uint32_t r0, r1, r2, r3;
                LDMX4(r0, r1, r2, r3, sW1 + (uint32_t)(brow * 72 + bcol) * 2);
                bfr[bt * 2][0] = r0; bfr[bt * 2][1] = r1;
                bfr[bt * 2 + 1][0] = r2; bfr[bt * 2 + 1][1] = r3;
            }
#pragma unroll
            for (int mt = 0; mt < 2; mt++)
#pragma unroll
                for (int nt = 0; nt < 8; nt++)
                    MMA16816(acc[mt][nt], af[mt], bfr[nt]);
        }
        // bias + relu + pack to H
#pragma unroll
        for (int mt = 0; mt < 2; mt++) {
            int m = wm * 32 + mt * 16 + cr;
#pragma unroll
            for (int nt = 0; nt < 8; nt++) {
                int ncol = nb + nt * 8 + cn;
                float bv0 = b1s[ncol], bv1 = b1s[ncol + 1];
                *(uint32_t*)&Hb[m * 264 + ncol] =
                    packbf2(fmaxf(acc[mt][nt][0] + bv0, 0.f),
                            fmaxf(acc[mt][nt][1] + bv1, 0.f));
                *(uint32_t*)&Hb[(m + 8) * 264 + ncol] =
                    packbf2(fmaxf(acc[mt][nt][2] + bv0, 0.f),
                            fmaxf(acc[mt][nt][3] + bv1, 0.f));
            }
        }
    }
    __syncthreads();

    // GEMM2: C[128 tok][64 out] = H @ W2b^T  (K=256)
    float acc2[2][4][4];
#pragma unroll
    for (int mt = 0; mt < 2; mt++)
#pragma unroll
        for (int nt = 0; nt < 4; nt++)
#pragma unroll
            for (int q = 0; q < 4; q++) acc2[mt][nt][q] = 0.f;
#pragma unroll
    for (int kk = 0; kk < 16; kk++) {
        uint32_t af[2][4], bfr[4][2];
#pragma unroll
        for (int mt = 0; mt < 2; mt++) {
            int arow = wm * 32 + mt * 16 + (mat & 1) * 8 + mr;
            int acol = kk * 16 + (mat >> 1) * 8;
            LDMX4(af[mt][0], af[mt][1], af[mt][2], af[mt][3],
                  sH + (uint32_t)(arow * 264 + acol) * 2);
        }
#pragma unroll
        for (int bt = 0; bt < 2; bt++) {
            int brow = wn * 32 + bt * 16 + (mat >> 1) * 8 + mr;
            int bcol = kk * 16 + (mat & 1) * 8;
            uint32_t r0, r1, r2, r3;
            LDMX4(r0, r1, r2, r3, sW2 + (uint32_t)(brow * 264 + bcol) * 2);
            bfr[bt * 2][0] = r0; bfr[bt * 2][1] = r1;
            bfr[bt * 2 + 1][0] = r2; bfr[bt * 2 + 1][1] = r3;
        }
#pragma unroll
        for (int mt = 0; mt < 2; mt++)
#pragma unroll
            for (int nt = 0; nt < 4; nt++)
                MMA16816(acc2[mt][nt], af[mt], bfr[nt]);
    }

    // epilogue: out = tmid + b2 + C
#pragma unroll
    for (int mt = 0; mt < 2; mt++) {
        int m = wm * 32 + mt * 16 + cr;
#pragma unroll
        for (int nt = 0; nt < 4; nt++) {
            int ncol = wn * 32 + nt * 8 + cn;
            float bv0 = b2s[ncol], bv1 = b2s[ncol + 1];
            {
                int t = t0 + m;
                float2 r = *(const float2*)(g_tmid + (size_t)t * 64 + ncol);
                *(float2*)(out + (size_t)t * 64 + ncol) =
                    make_float2(r.x + bv0 + acc2[mt][nt][0], r.y + bv1 + acc2[mt][nt][1]);
            }
            {
                int t = t0 + m + 8;
                float2 r = *(const float2*)(g_tmid + (size_t)t * 64 + ncol);
                *(float2*)(out + (size_t)t * 64 + ncol) =
                    make_float2(r.x + bv0 + acc2[mt][nt][2], r.y + bv1 + acc2[mt][nt][3]);
            }
        }
    }
}

// ---------------- launch ----------------
#define SM3_BYTES ((64 * 132 + 64 * 64) * 4)

extern "C" void kernel_launch(void* const* d_in, const int* in_sizes, int n_in,
                              void* d_out, int out_size) {
    (void)in_sizes; (void)n_in; (void)out_size;
    const float* src  = (const float*)d_in[0];
    const float* tgt  = (const float*)d_in[1];
    const float* Wp   = (const float*)d_in[2];
    const float* bp   = (const float*)d_in[3];
    const float* Wm   = (const float*)d_in[4];
    const float* bm   = (const float*)d_in[5];
    const float* Wo   = (const float*)d_in[6];
    const float* bo   = (const float*)d_in[7];
    const float* W1   = (const float*)d_in[8];
    const float* b1   = (const float*)d_in[9];
    const float* W2   = (const float*)d_in[10];
    const float* b2   = (const float*)d_in[11];
    const float* gn   = (const float*)d_in[12];
    const float* btn  = (const float*)d_in[13];
    const float* g1   = (const float*)d_in[14];
    const float* bt1  = (const float*)d_in[15];
    const float* g2   = (const float*)d_in[16];
    const float* bt2  = (const float*)d_in[17];
    float* out = (float*)d_out;

    static bool inited = false;
    if (!inited) {
        cudaFuncSetAttribute(k3_vproj,    cudaFuncAttributeMaxDynamicSharedMemorySize, SM3_BYTES);
        cudaFuncSetAttribute(k4_hmma,     cudaFuncAttributeMaxDynamicSharedMemorySize, K4_SMEM);
        cudaFuncSetAttribute(k5_oproj,    cudaFuncAttributeMaxDynamicSharedMemorySize, SM3_BYTES);
        cudaFuncSetAttribute(k6_ffn_hmma, cudaFuncAttributeMaxDynamicSharedMemorySize, K6_SMEM);
        inited = true;
    }

    k0_wconv<<<64, 256>>>(W1, W2);
    k1_sym_ln_logits<<<4608, 256>>>(src, Wp, bp, gn, btn);
    k2_softmax<<<(HEADS * LL + 7) / 8, 256>>>();
    k3_vproj<<<NT / 128, 256, SM3_BYTES>>>(tgt, Wm, bm, g1, bt1);
    k4_hmma<<<dim3(NCC / 128, LL / 128, HEADS), 256, K4_SMEM>>>();
    k5_oproj<<<NT / 128, 256, SM3_BYTES>>>(tgt, Wo, bo);
    k6_ffn_hmma<<<NT / 128, 256, K6_SMEM>>>(b1, b2, g2, bt2, out);
}

// round 17
// speedup vs baseline: 6.9197x; 1.2691x over previous
#include <cuda_runtime.h>
#include <cuda_fp16.h>
#include <cstdint>

#define LL 384
#define NN 512
#define DIN 128
#define DOUT 64
#define HEADS 4
#define CHN 16
#define DFF 256
#define NCC (NN*CHN)       /* 8192 */
#define NT (NN*LL)         /* 196608 */
#define EPSV 1e-5f

typedef unsigned long long u64t;

__device__ __forceinline__ uint32_t smem_u32(const void* p) {
    uint32_t a;
    asm("{ .reg .u64 t; cvta.to.shared.u64 t, %1; cvt.u32.u64 %0, t; }" : "=r"(a) : "l"(p));
    return a;
}
__device__ __forceinline__ void cp_async16(uint32_t s, const void* g) {
    asm volatile("cp.async.cg.shared.global [%0], [%1], 16;" :: "r"(s), "l"(g));
}
#define CP_COMMIT() asm volatile("cp.async.commit_group;" ::: "memory")
#define CP_WAIT0()  asm volatile("cp.async.wait_group 0;" ::: "memory")

#define LDMX4(d0, d1, d2, d3, addr) \
    asm volatile("ldmatrix.sync.aligned.m8n8.x4.shared.b16 {%0,%1,%2,%3}, [%4];" \
        : "=r"(d0), "=r"(d1), "=r"(d2), "=r"(d3) : "r"(addr))

#define MMAH(c, a, b) \
    asm volatile("mma.sync.aligned.m16n8k16.row.col.f32.f16.f16.f32 " \
        "{%0,%1,%2,%3}, {%4,%5,%6,%7}, {%8,%9}, {%0,%1,%2,%3};" \
        : "+f"((c)[0]), "+f"((c)[1]), "+f"((c)[2]), "+f"((c)[3]) \
        : "r"((a)[0]), "r"((a)[1]), "r"((a)[2]), "r"((a)[3]), "r"((b)[0]), "r"((b)[1]))

__device__ __forceinline__ uint32_t packh2(float x, float y) {
    __half2 h = __floats2half2_rn(x, y);
    return *(uint32_t*)&h;
}

// ---------------- scratch ----------------
__device__ float g_attn[HEADS * LL * LL];                   // fp32 logits [h][l][k]
__device__ __half g_attn_h[(size_t)HEADS * LL * LL];        // A fp16 [h][l][k]
__device__ __half g_vt_h[(size_t)HEADS * NCC * LL];         // B fp16 [h][j][k]
__device__ float g_o [(size_t)HEADS * LL * NN * CHN];       // [h][l][n*C+c]
__device__ float g_tmid[(size_t)NT * DOUT];                 // [n*L+l][d]
__device__ __half g_W1h[DFF * DOUT];                        // [256 hid][64 in]
__device__ __half g_W2h[DOUT * DFF];                        // [64 out][256 hid]
__device__ __half g_Wmh[DOUT * DOUT];                       // [64 n][64 k]
__device__ __half g_Woh[DOUT * DOUT];                       // [64 n][64 k]

// ---------------- K0: weight transpose+convert ----------------
__global__ void k0_wconv(const float* __restrict__ W1, const float* __restrict__ W2,
                         const float* __restrict__ Wm, const float* __restrict__ Wo) {
    int t = blockIdx.x * 256 + threadIdx.x;
    int stride = gridDim.x * 256;
    for (int i = t; i < DFF * DOUT; i += stride) {
        int n = i >> 6, k = i & 63;
        g_W1h[i] = __float2half_rn(W1[k * DFF + n]);
    }
    for (int i = t; i < DOUT * DFF; i += stride) {
        int n = i >> 8, k = i & 255;
        g_W2h[i] = __float2half_rn(W2[k * DOUT + n]);
    }
    for (int i = t; i < DOUT * DOUT; i += stride) {
        int n = i >> 6, k = i & 63;
        g_Wmh[i] = __float2half_rn(Wm[k * DOUT + n]);
        g_Woh[i] = __float2half_rn(Wo[k * DOUT + n]);
    }
}

// ---------------- K1: symmetrize + LayerNorm(128) + pair logits (i<=j only) ----------------
__global__ void k1_sym_ln_logits(const float* __restrict__ src,
                                 const float* __restrict__ Wp,
                                 const float* __restrict__ bp,
                                 const float* __restrict__ gn,
                                 const float* __restrict__ btn) {
    int lane = threadIdx.x & 31;
    int warp = (blockIdx.x * blockDim.x + threadIdx.x) >> 5;
    int nw   = (gridDim.x * blockDim.x) >> 5;
    int d0 = lane * 4;

    float gg[4], bb[4], wp[4][4], bph[4];
#pragma unroll
    for (int q = 0; q < 4; q++) { gg[q] = gn[d0 + q]; bb[q] = btn[d0 + q]; }
#pragma unroll
    for (int q = 0; q < 4; q++)
#pragma unroll
        for (int h = 0; h < 4; h++) wp[q][h] = Wp[(d0 + q) * 4 + h];
#pragma unroll
    for (int h = 0; h < 4; h++) bph[h] = bp[h];

    for (int p = warp; p < LL * LL; p += nw) {
        int i = p / LL, j = p - i * LL;
        if (i > j) continue;
        float4 a = *(const float4*)(src + ((size_t)i * LL + j) * DIN + d0);
        float4 b = *(const float4*)(src + ((size_t)j * LL + i) * DIN + d0);
        float s[4];
        s[0] = 0.5f * (a.x + b.x); s[1] = 0.5f * (a.y + b.y);
        s[2] = 0.5f * (a.z + b.z); s[3] = 0.5f * (a.w + b.w);

        float m = s[0] + s[1] + s[2] + s[3];
#pragma unroll
        for (int o = 16; o > 0; o >>= 1) m += __shfl_xor_sync(~0u, m, o);
        m *= (1.0f / 128.0f);

        float dv[4], var = 0.f;
#pragma unroll
        for (int q = 0; q < 4; q++) { dv[q] = s[q] - m; var += dv[q] * dv[q]; }
#pragma unroll
        for (int o = 16; o > 0; o >>= 1) var += __shfl_xor_sync(~0u, var, o);
        float inv = rsqrtf(var * (1.0f / 128.0f) + EPSV);

        float lg[4] = {0.f, 0.f, 0.f, 0.f};
#pragma unroll
        for (int q = 0; q < 4; q++) {
            float y = gg[q] * dv[q] * inv + bb[q];
#pragma unroll
            for (int h = 0; h < 4; h++) lg[h] += y * wp[q][h];
        }
#pragma unroll
        for (int h = 0; h < 4; h++)
#pragma unroll
            for (int o = 16; o > 0; o >>= 1) lg[h] += __shfl_xor_sync(~0u, lg[h], o);

        if (lane == 0) {
#pragma unroll
            for (int h = 0; h < 4; h++) {
                float v = lg[h] + bph[h];
                g_attn[h * LL * LL + j * LL + i] = v;
                g_attn[h * LL * LL + i * LL + j] = v;
            }
        }
    }
}

// ---------------- K2: softmax over k; emit fp16 A ----------------
__global__ void k2_softmax() {
    int lane = threadIdx.x & 31;
    int row  = (blockIdx.x * blockDim.x + threadIdx.x) >> 5;
    if (row >= HEADS * LL) return;
    const float* p = g_attn + (size_t)row * LL;
    float x[12];
    float mx = -1e30f;
#pragma unroll
    for (int q = 0; q < 12; q++) { x[q] = p[lane + q * 32]; mx = fmaxf(mx, x[q]); }
#pragma unroll
    for (int o = 16; o > 0; o >>= 1) mx = fmaxf(mx, __shfl_xor_sync(~0u, mx, o));
    float s = 0.f;
#pragma unroll
    for (int q = 0; q < 12; q++) { x[q] = __expf(x[q] - mx); s += x[q]; }
#pragma unroll
    for (int o = 16; o > 0; o >>= 1) s += __shfl_xor_sync(~0u, s, o);
    float rr = 1.0f / s;

    __half* arow = g_attn_h + (size_t)row * LL;
#pragma unroll
    for (int q = 0; q < 12; q++)
        arow[lane + q * 32] = __float2half_rn(x[q] * rr);
}

// ---------------- K3: v = LN(tgt) @ Wm + bm -> fp16 B [h][j][k]  (HMMA) ----------------
// smem (halves): Xh[128][72] @0, Wms[64][72] @9216, Vt[64][136] @13824, bms(f32 x64) @22528
#define K3_SMEM ((22528 + 128) * 2)
__global__ void __launch_bounds__(256) k3_vproj(const float* __restrict__ tgt,
                                                const float* __restrict__ bm,
                                                const float* __restrict__ g1,
                                                const float* __restrict__ bt1) {
    extern __shared__ __half smh3[];
    __half* Xh  = smh3;
    __half* Wms = smh3 + 9216;
    __half* Vt  = smh3 + 13824;
    float* bms  = (float*)(smh3 + 22528);
    uint32_t sX = smem_u32(Xh), sW = smem_u32(Wms);

    int tid = threadIdx.x, lane = tid & 31, w = tid >> 5;
    int t0 = blockIdx.x * 128;
    int n = blockIdx.x / 3, kbase = (blockIdx.x % 3) * 128;

    // stage Wm^T fp16 (64x64 -> stride 72)
#pragma unroll
    for (int i = 0; i < 2; i++) {
        int idx = tid + i * 256;
        int row = idx >> 3, ch = idx & 7;
        cp_async16(sW + (uint32_t)(row * 72 + ch * 8) * 2, g_Wmh + row * 64 + ch * 8);
    }
    CP_COMMIT();
    if (tid < 64) bms[tid] = bm[tid];

    // LN -> Xh fp16 [token][feat]
    float g1a = g1[lane * 2], g1b = g1[lane * 2 + 1];
    float ba = bt1[lane * 2], bb = bt1[lane * 2 + 1];
#pragma unroll 4
    for (int s = 0; s < 16; s++) {
        int tt = w * 16 + s;
        float2 x = *(const float2*)(tgt + (size_t)(t0 + tt) * 64 + lane * 2);
        float m = x.x + x.y;
#pragma unroll
        for (int o = 16; o > 0; o >>= 1) m += __shfl_xor_sync(~0u, m, o);
        m *= (1.0f / 64.0f);
        float dx0 = x.x - m, dx1 = x.y - m;
        float v = dx0 * dx0 + dx1 * dx1;
#pragma unroll
        for (int o = 16; o > 0; o >>= 1) v += __shfl_xor_sync(~0u, v, o);
        float inv = rsqrtf(v * (1.0f / 64.0f) + EPSV);
        *(uint32_t*)&Xh[tt * 72 + lane * 2] =
            packh2(g1a * dx0 * inv + ba, g1b * dx1 * inv + bb);
    }
    CP_WAIT0();
    __syncthreads();

    int wid = tid >> 5;
    int wm = wid & 3, wn = wid >> 2;
    int mat = lane >> 3, mr = lane & 7;
    int cr = lane >> 2, cn = (lane & 3) * 2;

    float acc[2][4][4];
#pragma unroll
    for (int mt = 0; mt < 2; mt++)
#pragma unroll
        for (int nt = 0; nt < 4; nt++)
#pragma unroll
            for (int q = 0; q < 4; q++) acc[mt][nt][q] = 0.f;

#pragma unroll
    for (int kk = 0; kk < 4; kk++) {
        uint32_t af[2][4], bfr[4][2];
#pragma unroll
        for (int mt = 0; mt < 2; mt++) {
            int arow = wm * 32 + mt * 16 + (mat & 1) * 8 + mr;
            int acol = kk * 16 + (mat >> 1) * 8;
            LDMX4(af[mt][0], af[mt][1], af[mt][2], af[mt][3],
                  sX + (uint32_t)(arow * 72 + acol) * 2);
        }
#pragma unroll
        for (int bt = 0; bt < 2; bt++) {
            int brow = wn * 32 + bt * 16 + (mat >> 1) * 8 + mr;
            int bcol = kk * 16 + (mat & 1) * 8;
            uint32_t r0, r1, r2, r3;
            LDMX4(r0, r1, r2, r3, sW + (uint32_t)(brow * 72 + bcol) * 2);
            bfr[bt * 2][0] = r0; bfr[bt * 2][1] = r1;
            bfr[bt * 2 + 1][0] = r2; bfr[bt * 2 + 1][1] = r3;
        }
#pragma unroll
        for (int mt = 0; mt < 2; mt++)
#pragma unroll
            for (int nt = 0; nt < 4; nt++)
                MMAH(acc[mt][nt], af[mt], bfr[nt]);
    }

    // bias + pack fp16 -> Vt[e][token] (transpose in smem)
#pragma unroll
    for (int mt = 0; mt < 2; mt++) {
        int m = wm * 32 + mt * 16 + cr;
#pragma unroll
        for (int nt = 0; nt < 4; nt++) {
            int e = wn * 32 + nt * 8 + cn;
            float b0 = bms[e], b1v = bms[e + 1];
            Vt[e * 136 + m]           = __float2half_rn(acc[mt][nt][0] + b0);
            Vt[(e + 1) * 136 + m]     = __float2half_rn(acc[mt][nt][1] + b1v);
            Vt[e * 136 + m + 8]       = __float2half_rn(acc[mt][nt][2] + b0);
            Vt[(e + 1) * 136 + m + 8] = __float2half_rn(acc[mt][nt][3] + b1v);
        }
    }
    __syncthreads();

    // cooperative row store: e -> head (e&3), channel (e>>2); 128 contiguous k
    {
        int e = tid >> 2, ch0 = tid & 3;
        __half* dst = g_vt_h + ((size_t)((e & 3) * NCC + n * 16 + (e >> 2))) * LL + kbase;
        const __half* srcr = Vt + e * 136;
#pragma unroll
        for (int c = 0; c < 4; c++)
            *(float4*)(dst + (ch0 + c * 4) * 8) = *(const float4*)(srcr + (ch0 + c * 4) * 8);
    }
}

// ---------------- K4: HMMA fp16 GEMM  C[h][l][j] = attn[h][l][k] * v[h][j][k]^T ----------------
#define K4_STR 72
#define K4_BUF (128 * K4_STR)
#define K4_SMEM (4 * K4_BUF * 2)
__global__ void __launch_bounds__(256) k4_hmma() {
    extern __shared__ __half smhb[];
    __half* As = smhb;
    __half* Bs = smhb + 2 * K4_BUF;
    int h = blockIdx.z, l0 = blockIdx.y * 128, j0 = blockIdx.x * 128;
    const __half* A = g_attn_h + ((size_t)h * LL + l0) * LL;
    const __half* B = g_vt_h + ((size_t)h * NCC + j0) * LL;

    int tid = threadIdx.x;
    int wid = tid >> 5, lane = tid & 31;
    int wm = wid & 1, wn = wid >> 1;
    uint32_t smA = smem_u32(As), smB = smem_u32(Bs);

    float acc[4][4][4];
#pragma unroll
    for (int mt = 0; mt < 4; mt++)
#pragma unroll
        for (int nt = 0; nt < 4; nt++)
#pragma unroll
            for (int q = 0; q < 4; q++) acc[mt][nt][q] = 0.f;

    int lrow = tid >> 3, lcg = tid & 7;
#pragma unroll
    for (int r = 0; r < 4; r++) {
        int row = lrow + r * 32;
        uint32_t so = (uint32_t)(row * K4_STR + lcg * 8) * 2;
        cp_async16(smA + so, A + (size_t)row * LL + lcg * 8);
        cp_async16(smB + so, B + (size_t)row * LL + lcg * 8);
    }
    CP_COMMIT();
    CP_WAIT0();
    __syncthreads();

    int mat = lane >> 3, mr = lane & 7;
    for (int t = 0; t < 6; t++) {
        int cur = t & 1;
        if (t < 5) {
            int k0 = (t + 1) * 64;
            uint32_t bo = (uint32_t)(cur ^ 1) * K4_BUF * 2;
#pragma unroll
            for (int r = 0; r < 4; r++) {
                int row = lrow + r * 32;
                uint32_t so = bo + (uint32_t)(row * K4_STR + lcg * 8) * 2;
                cp_async16(smA + so, A + (size_t)row * LL + k0 + lcg * 8);
                cp_async16(smB + so, B + (size_t)row * LL + k0 + lcg * 8);
            }
            CP_COMMIT();
        }
        uint32_t baseA = smA + (uint32_t)cur * K4_BUF * 2;
        uint32_t baseB = smB + (uint32_t)cur * K4_BUF * 2;
#pragma unroll
        for (int kk = 0; kk < 4; kk++) {
            uint32_t af[4][4], bfr[4][2];
#pragma unroll
            for (int mt = 0; mt < 4; mt++) {
                int arow = wm * 64 + mt * 16 + (mat & 1) * 8 + mr;
                int acol = kk * 16 + (mat >> 1) * 8;
                LDMX4(af[mt][0], af[mt][1], af[mt][2], af[mt][3],
                      baseA + (uint32_t)(arow * K4_STR + acol) * 2);
            }
#pragma unroll
            for (int bt = 0; bt < 2; bt++) {
                int brow = wn * 32 + bt * 16 + (mat >> 1) * 8 + mr;
                int bcol = kk * 16 + (mat & 1) * 8;
                uint32_t r0, r1, r2, r3;
                LDMX4(r0, r1, r2, r3, baseB + (uint32_t)(brow * K4_STR + bcol) * 2);
                bfr[bt * 2][0] = r0; bfr[bt * 2][1] = r1;
                bfr[bt * 2 + 1][0] = r2; bfr[bt * 2 + 1][1] = r3;
            }
#pragma unroll
            for (int mt = 0; mt < 4; mt++)
#pragma unroll
                for (int nt = 0; nt < 4; nt++)
                    MMAH(acc[mt][nt], af[mt], bfr[nt]);
        }
        if (t < 5) CP_WAIT0();
        __syncthreads();
    }

    int cr = lane >> 2, cn = (lane & 3) * 2;
#pragma unroll
    for (int mt = 0; mt < 4; mt++) {
        int m = l0 + wm * 64 + mt * 16 + cr;
        float* p0 = g_o + ((size_t)h * LL + m) * NCC + j0 + wn * 32 + cn;
        float* p1 = p0 + 8 * NCC;
#pragma unroll
        for (int nt = 0; nt < 4; nt++) {
            *(float2*)(p0 + nt * 8) = make_float2(acc[mt][nt][0], acc[mt][nt][1]);
            *(float2*)(p1 + nt * 8) = make_float2(acc[mt][nt][2], acc[mt][nt][3]);
        }
    }
}

// ---------------- K5: tmid = tgt + gather(g_o) @ Wo + bo  (HMMA) ----------------
// smem (halves): Xh[128][72] @0, Wos[64][72] @9216, bos(f32 x64) @13824
#define K5_SMEM ((13824 + 128) * 2)
__global__ void __launch_bounds__(256) k5_oproj(const float* __restrict__ tgt,
                                                const float* __restrict__ bo) {
    extern __shared__ __half smh5[];
    __half* Xh  = smh5;
    __half* Wos = smh5 + 9216;
    float* bos  = (float*)(smh5 + 13824);
    uint32_t sX = smem_u32(Xh), sW = smem_u32(Wos);

    int tid = threadIdx.x, lane = tid & 31;
    int t0 = blockIdx.x * 128;
    int n = blockIdx.x / 3, lbase = (blockIdx.x % 3) * 128;

#pragma unroll
    for (int i = 0; i < 2; i++) {
        int idx = tid + i * 256;
        int row = idx >> 3, ch = idx & 7;
        cp_async16(sW + (uint32_t)(row * 72 + ch * 8) * 2, g_Woh + row * 64 + ch * 8);
    }
    CP_COMMIT();
    if (tid < 64) bos[tid] = bo[tid];

    // gather g_o -> Xh fp16 [token][e]
    {
        int c4 = tid & 3, hh = (tid >> 2) & 3, tg = tid >> 4;
        int e0 = c4 * 16 + hh;
#pragma unroll
        for (int p = 0; p < 8; p++) {
            int tt = p * 16 + tg;
            int l = lbase + tt;
            float4 v = *(const float4*)(g_o + (((size_t)hh * LL + l) * NN + n) * CHN + c4 * 4);
            Xh[tt * 72 + e0]      = __float2half_rn(v.x);
            Xh[tt * 72 + e0 + 4]  = __float2half_rn(v.y);
            Xh[tt * 72 + e0 + 8]  = __float2half_rn(v.z);
            Xh[tt * 72 + e0 + 12] = __float2half_rn(v.w);
        }
    }
    CP_WAIT0();
    __syncthreads();

    int wid = tid >> 5;
    int wm = wid & 3, wn = wid >> 2;
    int mat = lane >> 3, mr = lane & 7;
    int cr = lane >> 2, cn = (lane & 3) * 2;

    float acc[2][4][4];
#pragma unroll
    for (int mt = 0; mt < 2; mt++)
#pragma unroll
        for (int nt = 0; nt < 4; nt++)
#pragma unroll
            for (int q = 0; q < 4; q++) acc[mt][nt][q] = 0.f;

#pragma unroll
    for (int kk = 0; kk < 4; kk++) {
        uint32_t af[2][4], bfr[4][2];
#pragma unroll
        for (int mt = 0; mt < 2; mt++) {
            int arow = wm * 32 + mt * 16 + (mat & 1) * 8 + mr;
            int acol = kk * 16 + (mat >> 1) * 8;
            LDMX4(af[mt][0], af[mt][1], af[mt][2], af[mt][3],
                  sX + (uint32_t)(arow * 72 + acol) * 2);
        }
#pragma unroll
        for (int bt = 0; bt < 2; bt++) {
            int brow = wn * 32 + bt * 16 + (mat >> 1) * 8 + mr;
            int bcol = kk * 16 + (mat & 1) * 8;
            uint32_t r0, r1, r2, r3;
            LDMX4(r0, r1, r2, r3, sW + (uint32_t)(brow * 72 + bcol) * 2);
            bfr[bt * 2][0] = r0; bfr[bt * 2][1] = r1;
            bfr[bt * 2 + 1][0] = r2; bfr[bt * 2 + 1][1] = r3;
        }
#pragma unroll
        for (int mt = 0; mt < 2; mt++)
#pragma unroll
            for (int nt = 0; nt < 4; nt++)
                MMAH(acc[mt][nt], af[mt], bfr[nt]);
    }

    // epilogue: tmid = tgt + acc + bo
#pragma unroll
    for (int mt = 0; mt < 2; mt++) {
        int m = wm * 32 + mt * 16 + cr;
#pragma unroll
        for (int nt = 0; nt < 4; nt++) {
            int ncol = wn * 32 + nt * 8 + cn;
            float b0 = bos[ncol], b1v = bos[ncol + 1];
            {
                int t = t0 + m;
                float2 r = *(const float2*)(tgt + (size_t)t * 64 + ncol);
                *(float2*)(g_tmid + (size_t)t * 64 + ncol) =
                    make_float2(r.x + b0 + acc[mt][nt][0], r.y + b1v + acc[mt][nt][1]);
            }
            {
                int t = t0 + m + 8;
                float2 r = *(const float2*)(tgt + (size_t)t * 64 + ncol);
                *(float2*)(g_tmid + (size_t)t * 64 + ncol) =
                    make_float2(r.x + b0 + acc[mt][nt][2], r.y + b1v + acc[mt][nt][3]);
            }
        }
    }
}

// ---------------- K6: HMMA FFN: out = tmid + relu(LN(tmid)@W1+b1)@W2+b2 ----------------
#define K6_XOFF 0
#define K6_W1OFF (128 * 72)
#define K6_W2OFF (K6_W1OFF + 256 * 72)
#define K6_HOFF  (K6_W2OFF + 64 * 264)
#define K6_HF_ELEMS (K6_HOFF + 128 * 264)
#define K6_SMEM (K6_HF_ELEMS * 2 + 256 * 4 + 64 * 4)
__global__ void __launch_bounds__(256, 1) k6_ffn_hmma(const float* __restrict__ b1,
                                                      const float* __restrict__ b2,
                                                      const float* __restrict__ g2,
                                                      const float* __restrict__ bt2,
                                                      float* __restrict__ out) {
    extern __shared__ __half sm6h[];
    __half* Xb  = sm6h + K6_XOFF;
    __half* W1b = sm6h + K6_W1OFF;
    __half* W2b = sm6h + K6_W2OFF;
    __half* Hb  = sm6h + K6_HOFF;
    float* b1s = (float*)(sm6h + K6_HF_ELEMS);
    float* b2s = b1s + 256;
    uint32_t sX = smem_u32(Xb), sW1 = smem_u32(W1b), sW2 = smem_u32(W2b), sH = smem_u32(Hb);

    int tid = threadIdx.x;
    int lane = tid & 31, w = tid >> 5;
    int t0 = blockIdx.x * 128;

#pragma unroll
    for (int i = 0; i < 8; i++) {
        int idx = tid + i * 256;
        int row = idx >> 3, ch = idx & 7;
        cp_async16(sW1 + (uint32_t)(row * 72 + ch * 8) * 2, g_W1h + row * 64 + ch * 8);
    }
#pragma unroll
    for (int i = 0; i < 8; i++) {
        int idx = tid + i * 256;
        int row = idx >> 5, ch = idx & 31;
        cp_async16(sW2 + (uint32_t)(row * 264 + ch * 8) * 2, g_W2h + row * 256 + ch * 8);
    }
    CP_COMMIT();
    b1s[tid] = b1[tid];
    if (tid < 64) b2s[tid] = b2[tid];

    float g2a = g2[lane * 2], g2b = g2[lane * 2 + 1];
    float ba = bt2[lane * 2], bb = bt2[lane * 2 + 1];
#pragma unroll 4
    for (int s = 0; s < 16; s++) {
        int tt = w * 16 + s;
        float2 x = *(const float2*)(g_tmid + (size_t)(t0 + tt) * 64 + lane * 2);
        float m = x.x + x.y;
#pragma unroll
        for (int o = 16; o > 0; o >>= 1) m += __shfl_xor_sync(~0u, m, o);
        m *= (1.0f / 64.0f);
        float dx0 = x.x - m, dx1 = x.y - m;
        float v = dx0 * dx0 + dx1 * dx1;
#pragma unroll
        for (int o = 16; o > 0; o >>= 1) v += __shfl_xor_sync(~0u, v, o);
        float inv = rsqrtf(v * (1.0f / 64.0f) + EPSV);
        *(uint32_t*)&Xb[tt * 72 + lane * 2] =
            packh2(g2a * dx0 * inv + ba, g2b * dx1 * inv + bb);
    }
    CP_WAIT0();
    __syncthreads();

    int wid = tid >> 5;
    int wm = wid & 3, wn = wid >> 2;
    int mat = lane >> 3, mr = lane & 7;
    int cr = lane >> 2, cn = (lane & 3) * 2;

    // GEMM1: C[128 tok][256 hid], two n-passes of 128
#pragma unroll
    for (int np = 0; np < 2; np++) {
        float acc[2][8][4];
#pragma unroll
        for (int mt = 0; mt < 2; mt++)
#pragma unroll
            for (int nt = 0; nt < 8; nt++)
#pragma unroll
                for (int q = 0; q < 4; q++) acc[mt][nt][q] = 0.f;
        int nb = np * 128 + wn * 64;
#pragma unroll
        for (int kk = 0; kk < 4; kk++) {
            uint32_t af[2][4], bfr[8][2];
#pragma unroll
            for (int mt = 0; mt < 2; mt++) {
                int arow = wm * 32 + mt * 16 + (mat & 1) * 8 + mr;
                int acol = kk * 16 + (mat >> 1) * 8;
                LDMX4(af[mt][0], af[mt][1], af[mt][2], af[mt][3],
                      sX + (uint32_t)(arow * 72 + acol) * 2);
            }
#pragma unroll
            for (int bt = 0; bt < 4; bt++) {
                int brow = nb + bt * 16 + (mat >> 1) * 8 + mr;
                int bcol = kk * 16 + (mat & 1) * 8;
                uint32_t r0, r1, r2, r3;
                LDMX4(r0, r1, r2, r3, sW1 + (uint32_t)(brow * 72 + bcol) * 2);
                bfr[bt * 2][0] = r0; bfr[bt * 2][1] = r1;
                bfr[bt * 2 + 1][0] = r2; bfr[bt * 2 + 1][1] = r3;
            }
#pragma unroll
            for (int mt = 0; mt < 2; mt++)
#pragma unroll
                for (int nt = 0; nt < 8; nt++)
                    MMAH(acc[mt][nt], af[mt], bfr[nt]);
        }
#pragma unroll
        for (int mt = 0; mt < 2; mt++) {
            int m = wm * 32 + mt * 16 + cr;
#pragma unroll
            for (int nt = 0; nt < 8; nt++) {
                int ncol = nb + nt * 8 + cn;
                float bv0 = b1s[ncol], bv1 = b1s[ncol + 1];
                *(uint32_t*)&Hb[m * 264 + ncol] =
                    packh2(fmaxf(acc[mt][nt][0] + bv0, 0.f),
                           fmaxf(acc[mt][nt][1] + bv1, 0.f));
                *(uint32_t*)&Hb[(m + 8) * 264 + ncol] =
                    packh2(fmaxf(acc[mt][nt][2] + bv0, 0.f),
                           fmaxf(acc[mt][nt][3] + bv1, 0.f));
            }
        }
    }
    __syncthreads();

    // GEMM2: C[128 tok][64 out], K=256
    float acc2[2][4][4];
#pragma unroll
    for (int mt = 0; mt < 2; mt++)
#pragma unroll
        for (int nt = 0; nt < 4; nt++)
#pragma unroll
            for (int q = 0; q < 4; q++) acc2[mt][nt][q] = 0.f;
#pragma unroll
    for (int kk = 0; kk < 16; kk++) {
        uint32_t af[2][4], bfr[4][2];
#pragma unroll
        for (int mt = 0; mt < 2; mt++) {
            int arow = wm * 32 + mt * 16 + (mat & 1) * 8 + mr;
            int acol = kk * 16 + (mat >> 1) * 8;
            LDMX4(af[mt][0], af[mt][1], af[mt][2], af[mt][3],
                  sH + (uint32_t)(arow * 264 + acol) * 2);
        }
#pragma unroll
        for (int bt = 0; bt < 2; bt++) {
            int brow = wn * 32 + bt * 16 + (mat >> 1) * 8 + mr;
            int bcol = kk * 16 + (mat & 1) * 8;
            uint32_t r0, r1, r2, r3;
            LDMX4(r0, r1, r2, r3, sW2 + (uint32_t)(brow * 264 + bcol) * 2);
            bfr[bt * 2][0] = r0; bfr[bt * 2][1] = r1;
            bfr[bt * 2 + 1][0] = r2; bfr[bt * 2 + 1][1] = r3;
        }
#pragma unroll
        for (int mt = 0; mt < 2; mt++)
#pragma unroll
            for (int nt = 0; nt < 4; nt++)
                MMAH(acc2[mt][nt], af[mt], bfr[nt]);
    }

#pragma unroll
    for (int mt = 0; mt < 2; mt++) {
        int m = wm * 32 + mt * 16 + cr;
#pragma unroll
        for (int nt = 0; nt < 4; nt++) {
            int ncol = wn * 32 + nt * 8 + cn;
            float bv0 = b2s[ncol], bv1 = b2s[ncol + 1];
            {
                int t = t0 + m;
                float2 r = *(const float2*)(g_tmid + (size_t)t * 64 + ncol);
                *(float2*)(out + (size_t)t * 64 + ncol) =
                    make_float2(r.x + bv0 + acc2[mt][nt][0], r.y + bv1 + acc2[mt][nt][1]);
            }
            {
                int t = t0 + m + 8;
                float2 r = *(const float2*)(g_tmid + (size_t)t * 64 + ncol);
                *(float2*)(out + (size_t)t * 64 + ncol) =
                    make_float2(r.x + bv0 + acc2[mt][nt][2], r.y + bv1 + acc2[mt][nt][3]);
            }
        }
    }
}

// ---------------- launch ----------------
extern "C" void kernel_launch(void* const* d_in, const int* in_sizes, int n_in,
                              void* d_out, int out_size) {
    (void)in_sizes; (void)n_in; (void)out_size;
    const float* src  = (const float*)d_in[0];
    const float* tgt  = (const float*)d_in[1];
    const float* Wp   = (const float*)d_in[2];
    const float* bp   = (const float*)d_in[3];
    const float* Wm   = (const float*)d_in[4];
    const float* bm   = (const float*)d_in[5];
    const float* Wo   = (const float*)d_in[6];
    const float* bo   = (const float*)d_in[7];
    const float* W1   = (const float*)d_in[8];
    const float* b1   = (const float*)d_in[9];
    const float* W2   = (const float*)d_in[10];
    const float* b2   = (const float*)d_in[11];
    const float* gn   = (const float*)d_in[12];
    const float* btn  = (const float*)d_in[13];
    const float* g1   = (const float*)d_in[14];
    const float* bt1  = (const float*)d_in[15];
    const float* g2   = (const float*)d_in[16];
    const float* bt2  = (const float*)d_in[17];
    float* out = (float*)d_out;

    static bool inited = false;
    if (!inited) {
        cudaFuncSetAttribute(k3_vproj,    cudaFuncAttributeMaxDynamicSharedMemorySize, K3_SMEM);
        cudaFuncSetAttribute(k4_hmma,     cudaFuncAttributeMaxDynamicSharedMemorySize, K4_SMEM);
        cudaFuncSetAttribute(k5_oproj,    cudaFuncAttributeMaxDynamicSharedMemorySize, K5_SMEM);
        cudaFuncSetAttribute(k6_ffn_hmma, cudaFuncAttributeMaxDynamicSharedMemorySize, K6_SMEM);
        inited = true;
    }

    k0_wconv<<<64, 256>>>(W1, W2, Wm, Wo);
    k1_sym_ln_logits<<<4608, 256>>>(src, Wp, bp, gn, btn);
    k2_softmax<<<(HEADS * LL + 7) / 8, 256>>>();
    k3_vproj<<<NT / 128, 256, K3_SMEM>>>(tgt, bm, g1, bt1);
    k4_hmma<<<dim3(NCC / 128, LL / 128, HEADS), 256, K4_SMEM>>>();
    k5_oproj<<<NT / 128, 256, K5_SMEM>>>(tgt, bo);
    k6_ffn_hmma<<<NT / 128, 256, K6_SMEM>>>(b1, b2, g2, bt2, out);
}